// round 1
// baseline (speedup 1.0000x reference)
#include <cuda_runtime.h>

// Problem constants (fixed by the reference)
#define B_   4
#define S_   2048
#define D_   1024
#define H_   16
#define DH_  64
#define M_   (B_ * S_)      // 8192 rows
#define N1_  (3 * D_)       // 3072 qkv cols

// Scratch (no runtime allocation allowed)
__device__ float g_qkv[(size_t)M_ * N1_];   // 100.7 MB
__device__ float g_ctx[(size_t)M_ * D_];    //  33.6 MB

// ---------------------------------------------------------------------------
// SGEMM: C[M,N] = A[M,K] @ W[K,N] + bias[N]
// 128x128 block tile, BK=8, 256 threads, 8x8 per thread (split-column 4+4).
// ---------------------------------------------------------------------------
__global__ void __launch_bounds__(256)
sgemm_bias_kernel(const float* __restrict__ A, const float* __restrict__ W,
                  const float* __restrict__ bias, float* __restrict__ C,
                  int M, int N, int K)
{
    __shared__ float As[8][132];   // transposed A tile, padded -> conflict-free
    __shared__ float Bs[8][128];

    const int tid = threadIdx.x;
    const int tx  = tid & 15;
    const int ty  = tid >> 4;

    const int arow = tid >> 1;          // 0..127
    const int acol = (tid & 1) << 2;    // 0 or 4
    const int brow = tid >> 5;          // 0..7
    const int bcol = (tid & 31) << 2;   // 0..124

    const float* Ab = A + (size_t)blockIdx.y * 128 * K;
    const float* Wb = W + (size_t)blockIdx.x * 128;

    float acc[8][8];
#pragma unroll
    for (int i = 0; i < 8; i++)
#pragma unroll
        for (int j = 0; j < 8; j++) acc[i][j] = 0.f;

    for (int k0 = 0; k0 < K; k0 += 8) {
        float4 av = *(const float4*)(Ab + (size_t)arow * K + k0 + acol);
        As[acol + 0][arow] = av.x;
        As[acol + 1][arow] = av.y;
        As[acol + 2][arow] = av.z;
        As[acol + 3][arow] = av.w;
        *(float4*)&Bs[brow][bcol] =
            *(const float4*)(Wb + (size_t)(k0 + brow) * N + bcol);
        __syncthreads();

#pragma unroll
        for (int kk = 0; kk < 8; kk++) {
            float ar[8], br[8];
            *(float4*)&ar[0] = *(const float4*)&As[kk][ty * 8];
            *(float4*)&ar[4] = *(const float4*)&As[kk][ty * 8 + 4];
            *(float4*)&br[0] = *(const float4*)&Bs[kk][tx * 4];
            *(float4*)&br[4] = *(const float4*)&Bs[kk][64 + tx * 4];
#pragma unroll
            for (int i = 0; i < 8; i++)
#pragma unroll
                for (int j = 0; j < 8; j++)
                    acc[i][j] += ar[i] * br[j];
        }
        __syncthreads();
    }

    const int c0 = blockIdx.x * 128 + tx * 4;
    const float4 b0 = *(const float4*)(bias + c0);
    const float4 b1 = *(const float4*)(bias + c0 + 64);
#pragma unroll
    for (int i = 0; i < 8; i++) {
        const int row = blockIdx.y * 128 + ty * 8 + i;
        float4 v0 = make_float4(acc[i][0] + b0.x, acc[i][1] + b0.y,
                                acc[i][2] + b0.z, acc[i][3] + b0.w);
        float4 v1 = make_float4(acc[i][4] + b1.x, acc[i][5] + b1.y,
                                acc[i][6] + b1.z, acc[i][7] + b1.w);
        *(float4*)(C + (size_t)row * N + c0)      = v0;
        *(float4*)(C + (size_t)row * N + c0 + 64) = v1;
    }
}

// ---------------------------------------------------------------------------
// Flash attention (fp32, online softmax).
// grid = (S/64, H, B), block = 256 (16x16 thread tile).
// Thread (ty,tx) owns rows {ty+16i} and cols {tx+16j} (strided -> conflict-free).
// smem: Qs/Ks/Ps/Vs each [64][68] floats.
// ---------------------------------------------------------------------------
#define FL_STRIDE 68
#define FL_SMEM   (4 * 64 * FL_STRIDE * (int)sizeof(float))  // 69632 B

__global__ void __launch_bounds__(256)
flash_attn_kernel(const float* __restrict__ qkv, const int* __restrict__ mask,
                  float* __restrict__ ctx)
{
    extern __shared__ float sm[];
    float* Qs = sm;
    float* Ks = sm + 64 * FL_STRIDE;
    float* Ps = sm + 2 * 64 * FL_STRIDE;
    float* Vs = sm + 3 * 64 * FL_STRIDE;

    const int tid = threadIdx.x;
    const int tx  = tid & 15;
    const int ty  = tid >> 4;
    const int q0  = blockIdx.x * 64;
    const int h   = blockIdx.y;
    const int b   = blockIdx.z;

    const size_t rowbase = (size_t)b * S_;
    const float* qg = qkv + (rowbase + q0) * N1_ + h * DH_;
    const float* kg = qkv + rowbase * N1_ + D_ + h * DH_;
    const float* vg = qkv + rowbase * N1_ + 2 * D_ + h * DH_;

    // Load Q tile (row-major, float4)
#pragma unroll
    for (int i = 0; i < 4; i++) {
        int idx = tid + i * 256;          // float4 index 0..1023
        int r = idx >> 4;
        int d = (idx & 15) << 2;
        *(float4*)&Qs[r * FL_STRIDE + d] =
            *(const float4*)(qg + (size_t)r * N1_ + d);
    }

    float m[4], l[4], o[4][4];
#pragma unroll
    for (int i = 0; i < 4; i++) {
        m[i] = -1e30f; l[i] = 0.f;
#pragma unroll
        for (int j = 0; j < 4; j++) o[i][j] = 0.f;
    }

    for (int kt = 0; kt < S_ / 64; kt++) {
        const int k0 = kt * 64;
        __syncthreads();   // protect Ks/Vs/Ps reuse from previous iteration
#pragma unroll
        for (int i = 0; i < 4; i++) {
            int idx = tid + i * 256;
            int r = idx >> 4;
            int d = (idx & 15) << 2;
            *(float4*)&Ks[r * FL_STRIDE + d] =
                *(const float4*)(kg + (size_t)(k0 + r) * N1_ + d);
            *(float4*)&Vs[r * FL_STRIDE + d] =
                *(const float4*)(vg + (size_t)(k0 + r) * N1_ + d);
        }
        __syncthreads();

        // S = Q K^T (vectorized over d)
        float s[4][4];
#pragma unroll
        for (int i = 0; i < 4; i++)
#pragma unroll
            for (int j = 0; j < 4; j++) s[i][j] = 0.f;

#pragma unroll 4
        for (int d4 = 0; d4 < 64; d4 += 4) {
            float4 q[4], k[4];
#pragma unroll
            for (int i = 0; i < 4; i++)
                q[i] = *(const float4*)&Qs[(ty + 16 * i) * FL_STRIDE + d4];
#pragma unroll
            for (int j = 0; j < 4; j++)
                k[j] = *(const float4*)&Ks[(tx + 16 * j) * FL_STRIDE + d4];
#pragma unroll
            for (int i = 0; i < 4; i++)
#pragma unroll
                for (int j = 0; j < 4; j++)
                    s[i][j] += q[i].x * k[j].x + q[i].y * k[j].y +
                               q[i].z * k[j].z + q[i].w * k[j].w;
        }

        // scale + mask (exact reference semantics: masked -> -1000.0)
#pragma unroll
        for (int i = 0; i < 4; i++) {
            const int* mrow = mask + (size_t)(q0 + ty + 16 * i) * S_ + k0;
#pragma unroll
            for (int j = 0; j < 4; j++) {
                int mv = mrow[tx + 16 * j];
                s[i][j] = mv ? s[i][j] * 0.125f : -1000.0f;
            }
        }

        // online softmax per row (row group = 16 lanes with equal ty)
#pragma unroll
        for (int i = 0; i < 4; i++) {
            float mx = fmaxf(fmaxf(s[i][0], s[i][1]), fmaxf(s[i][2], s[i][3]));
            for (int off = 8; off >= 1; off >>= 1)
                mx = fmaxf(mx, __shfl_xor_sync(0xffffffffu, mx, off));
            const float mnew = fmaxf(m[i], mx);
            const float corr = __expf(m[i] - mnew);
            m[i] = mnew;
            float rsum = 0.f;
#pragma unroll
            for (int j = 0; j < 4; j++) {
                float p = __expf(s[i][j] - mnew);
                s[i][j] = p;
                rsum += p;
            }
            for (int off = 8; off >= 1; off >>= 1)
                rsum += __shfl_xor_sync(0xffffffffu, rsum, off);
            l[i] = l[i] * corr + rsum;
#pragma unroll
            for (int j = 0; j < 4; j++) o[i][j] *= corr;
#pragma unroll
            for (int j = 0; j < 4; j++)
                Ps[(ty + 16 * i) * FL_STRIDE + tx + 16 * j] = s[i][j];
        }
        __syncthreads();

        // O += P @ V
#pragma unroll 4
        for (int k = 0; k < 64; k++) {
            float pr[4], vr[4];
#pragma unroll
            for (int i = 0; i < 4; i++)
                pr[i] = Ps[(ty + 16 * i) * FL_STRIDE + k];
#pragma unroll
            for (int j = 0; j < 4; j++)
                vr[j] = Vs[k * FL_STRIDE + tx + 16 * j];
#pragma unroll
            for (int i = 0; i < 4; i++)
#pragma unroll
                for (int j = 0; j < 4; j++)
                    o[i][j] += pr[i] * vr[j];
        }
    }

    // normalize + store to ctx[b, s, h*64 + c]
#pragma unroll
    for (int i = 0; i < 4; i++) {
        const float inv = 1.0f / l[i];
        float* crow = ctx + (rowbase + q0 + ty + 16 * i) * (size_t)D_ + h * DH_;
#pragma unroll
        for (int j = 0; j < 4; j++)
            crow[tx + 16 * j] = o[i][j] * inv;
    }
}

// ---------------------------------------------------------------------------
extern "C" void kernel_launch(void* const* d_in, const int* in_sizes, int n_in,
                              void* d_out, int out_size)
{
    const float* x    = nullptr;
    const float* Wqkv = nullptr;
    const float* bqkv = nullptr;
    const float* Wout = nullptr;
    const float* bout = nullptr;
    const int*   mask = nullptr;

    for (int i = 0; i < n_in; i++) {
        long n = in_sizes[i];
        if      (n == (long)M_ * D_)   x    = (const float*)d_in[i];
        else if (n == (long)D_ * N1_)  Wqkv = (const float*)d_in[i];
        else if (n == (long)N1_)       bqkv = (const float*)d_in[i];
        else if (n == (long)D_ * D_)   Wout = (const float*)d_in[i];
        else if (n == (long)D_)        bout = (const float*)d_in[i];
        else if (n == (long)S_ * S_)   mask = (const int*)d_in[i];
    }

    float* qkv = nullptr;
    float* ctx = nullptr;
    cudaGetSymbolAddress((void**)&qkv, g_qkv);
    cudaGetSymbolAddress((void**)&ctx, g_ctx);

    cudaFuncSetAttribute(flash_attn_kernel,
                         cudaFuncAttributeMaxDynamicSharedMemorySize, FL_SMEM);

    dim3 g1(N1_ / 128, M_ / 128);             // 24 x 64
    sgemm_bias_kernel<<<g1, 256>>>(x, Wqkv, bqkv, qkv, M_, N1_, D_);

    dim3 g2(S_ / 64, H_, B_);                 // 32 x 16 x 4
    flash_attn_kernel<<<g2, 256, FL_SMEM>>>(qkv, mask, ctx);

    dim3 g3(D_ / 128, M_ / 128);              // 8 x 64
    sgemm_bias_kernel<<<g3, 256>>>(ctx, Wout, bout, (float*)d_out, M_, D_, D_);
}

// round 3
// speedup vs baseline: 1.2175x; 1.2175x over previous
#include <cuda_runtime.h>
#include <cuda_bf16.h>
#include <cstdint>

// Problem constants
#define B_   4
#define S_   2048
#define D_   1024
#define H_   16
#define DH_  64
#define M_   (B_ * S_)      // 8192
#define N1_  (3 * D_)       // 3072

// -------------------- scratch (no runtime alloc allowed) --------------------
__device__ float g_qkv[(size_t)M_ * N1_];
__device__ float g_ctx[(size_t)M_ * D_];
__device__ __nv_bfloat16 g_xhi[(size_t)M_ * D_];
__device__ __nv_bfloat16 g_xlo[(size_t)M_ * D_];
__device__ __nv_bfloat16 g_chi[(size_t)M_ * D_];
__device__ __nv_bfloat16 g_clo[(size_t)M_ * D_];
__device__ __nv_bfloat16 g_w1hi[(size_t)N1_ * D_];   // Wqkv^T [N,K]
__device__ __nv_bfloat16 g_w1lo[(size_t)N1_ * D_];
__device__ __nv_bfloat16 g_w2hi[(size_t)D_ * D_];    // Wout^T [N,K]
__device__ __nv_bfloat16 g_w2lo[(size_t)D_ * D_];

// -------------------- helpers --------------------
__device__ __forceinline__ uint32_t smem_u32(const void* p) {
    uint32_t a;
    asm("{ .reg .u64 t; cvta.to.shared.u64 t, %1; cvt.u32.u64 %0, t; }"
        : "=r"(a) : "l"(p));
    return a;
}
__device__ __forceinline__ void split1(float x, __nv_bfloat16& h, __nv_bfloat16& l) {
    h = __float2bfloat16(x);
    l = __float2bfloat16(x - __bfloat162float(h));
}
__device__ __forceinline__ void cp_async16(uint32_t dst, const void* src) {
    asm volatile("cp.async.cg.shared.global [%0], [%1], 16;"
                 :: "r"(dst), "l"(src) : "memory");
}
__device__ __forceinline__ void ldmat_x4(uint32_t addr, uint32_t& r0, uint32_t& r1,
                                         uint32_t& r2, uint32_t& r3) {
    asm volatile("ldmatrix.sync.aligned.m8n8.x4.shared.b16 {%0,%1,%2,%3}, [%4];"
                 : "=r"(r0), "=r"(r1), "=r"(r2), "=r"(r3) : "r"(addr));
}
__device__ __forceinline__ void mma16816(float* c, const uint32_t* a,
                                         const uint32_t* b) {
    asm volatile(
        "mma.sync.aligned.m16n8k16.row.col.f32.bf16.bf16.f32 "
        "{%0,%1,%2,%3}, {%4,%5,%6,%7}, {%8,%9}, {%0,%1,%2,%3};"
        : "+f"(c[0]), "+f"(c[1]), "+f"(c[2]), "+f"(c[3])
        : "r"(a[0]), "r"(a[1]), "r"(a[2]), "r"(a[3]), "r"(b[0]), "r"(b[1]));
}

// -------------------- split kernels --------------------
__global__ void __launch_bounds__(256)
split_kernel(const float* __restrict__ in, __nv_bfloat16* __restrict__ hi,
             __nv_bfloat16* __restrict__ lo)
{
    int i = (blockIdx.x * 256 + threadIdx.x) * 4;
    float4 v = *(const float4*)(in + i);
    union { __nv_bfloat16 b[4]; uint2 u; } H, L;
    split1(v.x, H.b[0], L.b[0]);
    split1(v.y, H.b[1], L.b[1]);
    split1(v.z, H.b[2], L.b[2]);
    split1(v.w, H.b[3], L.b[3]);
    *(uint2*)(hi + i) = H.u;
    *(uint2*)(lo + i) = L.u;
}

// W [K,N] row-major -> WT hi/lo [N,K]
__global__ void __launch_bounds__(256)
transpose_split_kernel(const float* __restrict__ W, __nv_bfloat16* __restrict__ hi,
                       __nv_bfloat16* __restrict__ lo, int K, int N)
{
    __shared__ float t[32][33];
    const int n0 = blockIdx.x * 32, k0 = blockIdx.y * 32;
    const int tx = threadIdx.x, ty = threadIdx.y;
#pragma unroll
    for (int i = ty; i < 32; i += 8)
        t[i][tx] = W[(size_t)(k0 + i) * N + n0 + tx];
    __syncthreads();
#pragma unroll
    for (int i = ty; i < 32; i += 8) {
        float x = t[tx][i];
        __nv_bfloat16 h, l;
        split1(x, h, l);
        size_t o = (size_t)(n0 + i) * K + k0 + tx;
        hi[o] = h; lo[o] = l;
    }
}

// -------------------- bf16-split GEMM via mma.sync (legacy HMMA) --------------------
// C[M,N] = (Ahi+Alo) @ (Bhi+Blo)^T + bias,  B stored [N,K] K-major.
// Block 128x128, BK=32, 256 thr (8 warps: 4 along M x 2 along N, 32x64 warp tiles).
#define BK_    32
#define PADK   40                       // bf16 per padded row (80 B)
#define TILE_E (128 * PADK)             // bf16 elems per tile
#define STG_E  (4 * TILE_E)             // Ahi,Alo,Bhi,Blo
#define GSMEM  (2 * STG_E * 2)          // 81920 bytes

__global__ void __launch_bounds__(256, 1)
gemm_mma_split(const __nv_bfloat16* __restrict__ Ahi, const __nv_bfloat16* __restrict__ Alo,
               const __nv_bfloat16* __restrict__ Bhi, const __nv_bfloat16* __restrict__ Blo,
               const float* __restrict__ bias, float* __restrict__ C,
               int N, int K)
{
    extern __shared__ __nv_bfloat16 smb[];
    const uint32_t sb = smem_u32(smb);
    const int tid  = threadIdx.x;
    const int lane = tid & 31;
    const int wid  = tid >> 5;
    const int wm   = wid & 3;            // 0..3 (M)
    const int wn   = wid >> 2;           // 0..1 (N)
    const int m0   = blockIdx.y * 128;
    const int n0   = blockIdx.x * 128;

    // cp.async stage loader: 2048 16B-chunks per stage, 8 per thread
    auto load_stage = [&](int st, int k0) {
#pragma unroll
        for (int i = 0; i < 8; i++) {
            int c    = tid + i * 256;
            int tile = c >> 9;           // 0:Ahi 1:Alo 2:Bhi 3:Blo
            int idx  = c & 511;
            int row  = idx >> 2;
            int seg  = idx & 3;
            const __nv_bfloat16* src;
            if      (tile == 0) src = Ahi + (size_t)(m0 + row) * K + k0 + seg * 8;
            else if (tile == 1) src = Alo + (size_t)(m0 + row) * K + k0 + seg * 8;
            else if (tile == 2) src = Bhi + (size_t)(n0 + row) * K + k0 + seg * 8;
            else                src = Blo + (size_t)(n0 + row) * K + k0 + seg * 8;
            uint32_t dst = sb + (uint32_t)(st * STG_E + tile * TILE_E +
                                           row * PADK + seg * 8) * 2;
            cp_async16(dst, src);
        }
        asm volatile("cp.async.commit_group;" ::: "memory");
    };

    float acc[2][8][4];
#pragma unroll
    for (int mt = 0; mt < 2; mt++)
#pragma unroll
        for (int nt = 0; nt < 8; nt++)
#pragma unroll
            for (int q = 0; q < 4; q++) acc[mt][nt][q] = 0.f;

    const int NC = K / BK_;
    load_stage(0, 0);

    const int lr = lane & 15;            // ldmatrix row lane
    const int lk = (lane >> 4) * 8;      // ldmatrix k-offset

    for (int c = 0; c < NC; c++) {
        if (c + 1 < NC) {
            load_stage((c + 1) & 1, (c + 1) * BK_);
            asm volatile("cp.async.wait_group 1;" ::: "memory");
        } else {
            asm volatile("cp.async.wait_group 0;" ::: "memory");
        }
        __syncthreads();

        const uint32_t so = sb + (uint32_t)((c & 1) * STG_E) * 2;
#pragma unroll
        for (int ks = 0; ks < 32; ks += 16) {
            uint32_t ahi[2][4], alo[2][4];
#pragma unroll
            for (int mt = 0; mt < 2; mt++) {
                uint32_t ad = so + (uint32_t)((wm * 32 + mt * 16 + lr) * PADK + ks + lk) * 2;
                ldmat_x4(ad, ahi[mt][0], ahi[mt][1], ahi[mt][2], ahi[mt][3]);
                ldmat_x4(ad + TILE_E * 2, alo[mt][0], alo[mt][1], alo[mt][2], alo[mt][3]);
            }
            uint32_t bhi[8][2], blo[8][2];
#pragma unroll
            for (int bt = 0; bt < 4; bt++) {
                uint32_t ad = so + (uint32_t)(2 * TILE_E) * 2 +
                              (uint32_t)((wn * 64 + bt * 16 + lr) * PADK + ks + lk) * 2;
                uint32_t r0, r1, r2, r3;
                ldmat_x4(ad, r0, r1, r2, r3);
                bhi[bt * 2][0] = r0; bhi[bt * 2][1] = r2;
                bhi[bt * 2 + 1][0] = r1; bhi[bt * 2 + 1][1] = r3;
                ldmat_x4(ad + TILE_E * 2, r0, r1, r2, r3);
                blo[bt * 2][0] = r0; blo[bt * 2][1] = r2;
                blo[bt * 2 + 1][0] = r1; blo[bt * 2 + 1][1] = r3;
            }
#pragma unroll
            for (int mt = 0; mt < 2; mt++)
#pragma unroll
                for (int nt = 0; nt < 8; nt++) {
                    mma16816(acc[mt][nt], ahi[mt], bhi[nt]);
                    mma16816(acc[mt][nt], ahi[mt], blo[nt]);
                    mma16816(acc[mt][nt], alo[mt], bhi[nt]);
                }
        }
        __syncthreads();
    }

    // epilogue: fragment layout c0,c1=(g,2t),(g,2t+1); c2,c3=row g+8
    const int g = lane >> 2, t = lane & 3;
#pragma unroll
    for (int mt = 0; mt < 2; mt++) {
        const int r0 = m0 + wm * 32 + mt * 16 + g;
#pragma unroll
        for (int nt = 0; nt < 8; nt++) {
            const int col = n0 + wn * 64 + nt * 8 + 2 * t;
            float2 bv = *(const float2*)(bias + col);
            float2 v0 = make_float2(acc[mt][nt][0] + bv.x, acc[mt][nt][1] + bv.y);
            float2 v1 = make_float2(acc[mt][nt][2] + bv.x, acc[mt][nt][3] + bv.y);
            *(float2*)(C + (size_t)r0 * N + col)       = v0;
            *(float2*)(C + (size_t)(r0 + 8) * N + col) = v1;
        }
    }
}

// -------------------- flash attention (fp32, unchanged) --------------------
#define FL_STRIDE 68
#define FL_SMEM   (4 * 64 * FL_STRIDE * (int)sizeof(float))

__global__ void __launch_bounds__(256)
flash_attn_kernel(const float* __restrict__ qkv, const int* __restrict__ mask,
                  float* __restrict__ ctx)
{
    extern __shared__ float smf[];
    float* Qs = smf;
    float* Ks = smf + 64 * FL_STRIDE;
    float* Ps = smf + 2 * 64 * FL_STRIDE;
    float* Vs = smf + 3 * 64 * FL_STRIDE;

    const int tid = threadIdx.x;
    const int tx  = tid & 15;
    const int ty  = tid >> 4;
    const int q0  = blockIdx.x * 64;
    const int h   = blockIdx.y;
    const int b   = blockIdx.z;

    const size_t rowbase = (size_t)b * S_;
    const float* qg = qkv + (rowbase + q0) * N1_ + h * DH_;
    const float* kg = qkv + rowbase * N1_ + D_ + h * DH_;
    const float* vg = qkv + rowbase * N1_ + 2 * D_ + h * DH_;

#pragma unroll
    for (int i = 0; i < 4; i++) {
        int idx = tid + i * 256;
        int r = idx >> 4;
        int d = (idx & 15) << 2;
        *(float4*)&Qs[r * FL_STRIDE + d] = *(const float4*)(qg + (size_t)r * N1_ + d);
    }

    float m[4], l[4], o[4][4];
#pragma unroll
    for (int i = 0; i < 4; i++) {
        m[i] = -1e30f; l[i] = 0.f;
#pragma unroll
        for (int j = 0; j < 4; j++) o[i][j] = 0.f;
    }

    for (int kt = 0; kt < S_ / 64; kt++) {
        const int k0 = kt * 64;
        __syncthreads();
#pragma unroll
        for (int i = 0; i < 4; i++) {
            int idx = tid + i * 256;
            int r = idx >> 4;
            int d = (idx & 15) << 2;
            *(float4*)&Ks[r * FL_STRIDE + d] =
                *(const float4*)(kg + (size_t)(k0 + r) * N1_ + d);
            *(float4*)&Vs[r * FL_STRIDE + d] =
                *(const float4*)(vg + (size_t)(k0 + r) * N1_ + d);
        }
        __syncthreads();

        float s[4][4];
#pragma unroll
        for (int i = 0; i < 4; i++)
#pragma unroll
            for (int j = 0; j < 4; j++) s[i][j] = 0.f;

#pragma unroll 4
        for (int d4 = 0; d4 < 64; d4 += 4) {
            float4 q[4], k[4];
#pragma unroll
            for (int i = 0; i < 4; i++)
                q[i] = *(const float4*)&Qs[(ty + 16 * i) * FL_STRIDE + d4];
#pragma unroll
            for (int j = 0; j < 4; j++)
                k[j] = *(const float4*)&Ks[(tx + 16 * j) * FL_STRIDE + d4];
#pragma unroll
            for (int i = 0; i < 4; i++)
#pragma unroll
                for (int j = 0; j < 4; j++)
                    s[i][j] += q[i].x * k[j].x + q[i].y * k[j].y +
                               q[i].z * k[j].z + q[i].w * k[j].w;
        }

#pragma unroll
        for (int i = 0; i < 4; i++) {
            const int* mrow = mask + (size_t)(q0 + ty + 16 * i) * S_ + k0;
#pragma unroll
            for (int j = 0; j < 4; j++) {
                int mv = mrow[tx + 16 * j];
                s[i][j] = mv ? s[i][j] * 0.125f : -1000.0f;
            }
        }

#pragma unroll
        for (int i = 0; i < 4; i++) {
            float mx = fmaxf(fmaxf(s[i][0], s[i][1]), fmaxf(s[i][2], s[i][3]));
            for (int off = 8; off >= 1; off >>= 1)
                mx = fmaxf(mx, __shfl_xor_sync(0xffffffffu, mx, off));
            const float mnew = fmaxf(m[i], mx);
            const float corr = __expf(m[i] - mnew);
            m[i] = mnew;
            float rsum = 0.f;
#pragma unroll
            for (int j = 0; j < 4; j++) {
                float p = __expf(s[i][j] - mnew);
                s[i][j] = p;
                rsum += p;
            }
            for (int off = 8; off >= 1; off >>= 1)
                rsum += __shfl_xor_sync(0xffffffffu, rsum, off);
            l[i] = l[i] * corr + rsum;
#pragma unroll
            for (int j = 0; j < 4; j++) o[i][j] *= corr;
#pragma unroll
            for (int j = 0; j < 4; j++)
                Ps[(ty + 16 * i) * FL_STRIDE + tx + 16 * j] = s[i][j];
        }
        __syncthreads();

#pragma unroll 4
        for (int k = 0; k < 64; k++) {
            float pr[4], vr[4];
#pragma unroll
            for (int i = 0; i < 4; i++)
                pr[i] = Ps[(ty + 16 * i) * FL_STRIDE + k];
#pragma unroll
            for (int j = 0; j < 4; j++)
                vr[j] = Vs[k * FL_STRIDE + tx + 16 * j];
#pragma unroll
            for (int i = 0; i < 4; i++)
#pragma unroll
                for (int j = 0; j < 4; j++)
                    o[i][j] += pr[i] * vr[j];
        }
    }

#pragma unroll
    for (int i = 0; i < 4; i++) {
        const float inv = 1.0f / l[i];
        float* crow = ctx + (rowbase + q0 + ty + 16 * i) * (size_t)D_ + h * DH_;
#pragma unroll
        for (int j = 0; j < 4; j++)
            crow[tx + 16 * j] = o[i][j] * inv;
    }
}

// -------------------- launch --------------------
extern "C" void kernel_launch(void* const* d_in, const int* in_sizes, int n_in,
                              void* d_out, int out_size)
{
    const float* x    = nullptr;
    const float* Wqkv = nullptr;
    const float* bqkv = nullptr;
    const float* Wout = nullptr;
    const float* bout = nullptr;
    const int*   mask = nullptr;

    for (int i = 0; i < n_in; i++) {
        long n = in_sizes[i];
        if      (n == (long)M_ * D_)   x    = (const float*)d_in[i];
        else if (n == (long)D_ * N1_)  Wqkv = (const float*)d_in[i];
        else if (n == (long)N1_)       bqkv = (const float*)d_in[i];
        else if (n == (long)D_ * D_)   Wout = (const float*)d_in[i];
        else if (n == (long)D_)        bout = (const float*)d_in[i];
        else if (n == (long)S_ * S_)   mask = (const int*)d_in[i];
    }

    float *qkv, *ctx;
    __nv_bfloat16 *xhi, *xlo, *chi, *clo, *w1hi, *w1lo, *w2hi, *w2lo;
    cudaGetSymbolAddress((void**)&qkv, g_qkv);
    cudaGetSymbolAddress((void**)&ctx, g_ctx);
    cudaGetSymbolAddress((void**)&xhi, g_xhi);
    cudaGetSymbolAddress((void**)&xlo, g_xlo);
    cudaGetSymbolAddress((void**)&chi, g_chi);
    cudaGetSymbolAddress((void**)&clo, g_clo);
    cudaGetSymbolAddress((void**)&w1hi, g_w1hi);
    cudaGetSymbolAddress((void**)&w1lo, g_w1lo);
    cudaGetSymbolAddress((void**)&w2hi, g_w2hi);
    cudaGetSymbolAddress((void**)&w2lo, g_w2lo);

    cudaFuncSetAttribute(flash_attn_kernel,
                         cudaFuncAttributeMaxDynamicSharedMemorySize, FL_SMEM);
    cudaFuncSetAttribute(gemm_mma_split,
                         cudaFuncAttributeMaxDynamicSharedMemorySize, GSMEM);

    // splits
    split_kernel<<<(M_ * D_) / (256 * 4), 256>>>(x, xhi, xlo);
    transpose_split_kernel<<<dim3(N1_ / 32, D_ / 32), dim3(32, 8)>>>(Wqkv, w1hi, w1lo, D_, N1_);
    transpose_split_kernel<<<dim3(D_ / 32, D_ / 32), dim3(32, 8)>>>(Wout, w2hi, w2lo, D_, D_);

    // qkv = x @ Wqkv + b
    gemm_mma_split<<<dim3(N1_ / 128, M_ / 128), 256, GSMEM>>>(
        xhi, xlo, w1hi, w1lo, bqkv, qkv, N1_, D_);

    // attention
    flash_attn_kernel<<<dim3(S_ / 64, H_, B_), 256, FL_SMEM>>>(qkv, mask, ctx);

    // out = ctx @ Wout + b
    split_kernel<<<(M_ * D_) / (256 * 4), 256>>>(ctx, chi, clo);
    gemm_mma_split<<<dim3(D_ / 128, M_ / 128), 256, GSMEM>>>(
        chi, clo, w2hi, w2lo, bout, (float*)d_out, D_, D_);
}

// round 4
// speedup vs baseline: 2.4696x; 2.0284x over previous
#include <cuda_runtime.h>
#include <cuda_bf16.h>
#include <cstdint>

// Problem constants
#define B_   4
#define S_   2048
#define D_   1024
#define H_   16
#define DH_  64
#define M_   (B_ * S_)      // 8192
#define N1_  (3 * D_)       // 3072

// -------------------- scratch --------------------
__device__ __nv_bfloat16 g_xhi[(size_t)M_ * D_];
__device__ __nv_bfloat16 g_xlo[(size_t)M_ * D_];
__device__ __nv_bfloat16 g_qkvhi[(size_t)M_ * N1_];
__device__ __nv_bfloat16 g_qkvlo[(size_t)M_ * N1_];
__device__ __nv_bfloat16 g_chi[(size_t)M_ * D_];
__device__ __nv_bfloat16 g_clo[(size_t)M_ * D_];
__device__ __nv_bfloat16 g_w1hi[(size_t)N1_ * D_];
__device__ __nv_bfloat16 g_w1lo[(size_t)N1_ * D_];
__device__ __nv_bfloat16 g_w2hi[(size_t)D_ * D_];
__device__ __nv_bfloat16 g_w2lo[(size_t)D_ * D_];

// -------------------- helpers --------------------
__device__ __forceinline__ uint32_t smem_u32(const void* p) {
    uint32_t a;
    asm("{ .reg .u64 t; cvta.to.shared.u64 t, %1; cvt.u32.u64 %0, t; }"
        : "=r"(a) : "l"(p));
    return a;
}
__device__ __forceinline__ void cp_async16(uint32_t dst, const void* src) {
    asm volatile("cp.async.cg.shared.global [%0], [%1], 16;"
                 :: "r"(dst), "l"(src) : "memory");
}
__device__ __forceinline__ void ldmat_x4(uint32_t addr, uint32_t& r0, uint32_t& r1,
                                         uint32_t& r2, uint32_t& r3) {
    asm volatile("ldmatrix.sync.aligned.m8n8.x4.shared.b16 {%0,%1,%2,%3}, [%4];"
                 : "=r"(r0), "=r"(r1), "=r"(r2), "=r"(r3) : "r"(addr));
}
__device__ __forceinline__ void ldmat_x4t(uint32_t addr, uint32_t& r0, uint32_t& r1,
                                          uint32_t& r2, uint32_t& r3) {
    asm volatile("ldmatrix.sync.aligned.m8n8.x4.trans.shared.b16 {%0,%1,%2,%3}, [%4];"
                 : "=r"(r0), "=r"(r1), "=r"(r2), "=r"(r3) : "r"(addr));
}
__device__ __forceinline__ void mma16816(float* c, const uint32_t* a,
                                         const uint32_t* b) {
    asm volatile(
        "mma.sync.aligned.m16n8k16.row.col.f32.bf16.bf16.f32 "
        "{%0,%1,%2,%3}, {%4,%5,%6,%7}, {%8,%9}, {%0,%1,%2,%3};"
        : "+f"(c[0]), "+f"(c[1]), "+f"(c[2]), "+f"(c[3])
        : "r"(a[0]), "r"(a[1]), "r"(a[2]), "r"(a[3]), "r"(b[0]), "r"(b[1]));
}
__device__ __forceinline__ float ex2f(float x) {
    float y;
    asm("ex2.approx.ftz.f32 %0, %1;" : "=f"(y) : "f"(x));
    return y;
}
__device__ __forceinline__ uint32_t pack_bf2(float lo, float hi) {
    uint32_t d;
    asm("cvt.rn.bf16x2.f32 %0, %1, %2;" : "=r"(d) : "f"(hi), "f"(lo));
    return d;
}
// RN hi/lo split of a float pair into packed bf16x2 regs
__device__ __forceinline__ void split_pair(float a0, float a1,
                                           uint32_t& ph, uint32_t& pl) {
    ph = pack_bf2(a0, a1);
    float h0 = __uint_as_float(ph << 16);
    float h1 = __uint_as_float(ph & 0xFFFF0000u);
    pl = pack_bf2(a0 - h0, a1 - h1);
}
__device__ __forceinline__ void split1(float x, __nv_bfloat16& h, __nv_bfloat16& l) {
    h = __float2bfloat16(x);
    l = __float2bfloat16(x - __bfloat162float(h));
}

// -------------------- split / transpose prep kernels --------------------
__global__ void __launch_bounds__(256)
split_kernel(const float* __restrict__ in, __nv_bfloat16* __restrict__ hi,
             __nv_bfloat16* __restrict__ lo)
{
    int i = (blockIdx.x * 256 + threadIdx.x) * 4;
    float4 v = *(const float4*)(in + i);
    union { __nv_bfloat16 b[4]; uint2 u; } H, L;
    split1(v.x, H.b[0], L.b[0]);
    split1(v.y, H.b[1], L.b[1]);
    split1(v.z, H.b[2], L.b[2]);
    split1(v.w, H.b[3], L.b[3]);
    *(uint2*)(hi + i) = H.u;
    *(uint2*)(lo + i) = L.u;
}

__global__ void __launch_bounds__(256)
transpose_split_kernel(const float* __restrict__ W, __nv_bfloat16* __restrict__ hi,
                       __nv_bfloat16* __restrict__ lo, int K, int N)
{
    __shared__ float t[32][33];
    const int n0 = blockIdx.x * 32, k0 = blockIdx.y * 32;
    const int tx = threadIdx.x, ty = threadIdx.y;
#pragma unroll
    for (int i = ty; i < 32; i += 8)
        t[i][tx] = W[(size_t)(k0 + i) * N + n0 + tx];
    __syncthreads();
#pragma unroll
    for (int i = ty; i < 32; i += 8) {
        float x = t[tx][i];
        __nv_bfloat16 h, l;
        split1(x, h, l);
        size_t o = (size_t)(n0 + i) * K + k0 + tx;
        hi[o] = h; lo[o] = l;
    }
}

// -------------------- bf16-split GEMM (mma.sync) --------------------
// mode 0: C = fp32 out + bias.  mode 1: write split bf16 (Chi/Clo) of (acc+bias).
#define BK_    32
#define PADK   40
#define TILE_E (128 * PADK)
#define STG_E  (4 * TILE_E)
#define GSMEM  (2 * STG_E * 2)          // 81920 bytes

__global__ void __launch_bounds__(256, 2)
gemm_mma_split(const __nv_bfloat16* __restrict__ Ahi, const __nv_bfloat16* __restrict__ Alo,
               const __nv_bfloat16* __restrict__ Bhi, const __nv_bfloat16* __restrict__ Blo,
               const float* __restrict__ bias, float* __restrict__ C,
               __nv_bfloat16* __restrict__ Chi, __nv_bfloat16* __restrict__ Clo,
               int N, int K, int mode)
{
    extern __shared__ __nv_bfloat16 smb[];
    const uint32_t sb = smem_u32(smb);
    const int tid  = threadIdx.x;
    const int lane = tid & 31;
    const int wid  = tid >> 5;
    const int wm   = wid & 3;
    const int wn   = wid >> 2;
    const int m0   = blockIdx.y * 128;
    const int n0   = blockIdx.x * 128;

    auto load_stage = [&](int st, int k0) {
#pragma unroll
        for (int i = 0; i < 8; i++) {
            int c    = tid + i * 256;
            int tile = c >> 9;
            int idx  = c & 511;
            int row  = idx >> 2;
            int seg  = idx & 3;
            const __nv_bfloat16* src;
            if      (tile == 0) src = Ahi + (size_t)(m0 + row) * K + k0 + seg * 8;
            else if (tile == 1) src = Alo + (size_t)(m0 + row) * K + k0 + seg * 8;
            else if (tile == 2) src = Bhi + (size_t)(n0 + row) * K + k0 + seg * 8;
            else                src = Blo + (size_t)(n0 + row) * K + k0 + seg * 8;
            uint32_t dst = sb + (uint32_t)(st * STG_E + tile * TILE_E +
                                           row * PADK + seg * 8) * 2;
            cp_async16(dst, src);
        }
        asm volatile("cp.async.commit_group;" ::: "memory");
    };

    float acc[2][8][4];
#pragma unroll
    for (int mt = 0; mt < 2; mt++)
#pragma unroll
        for (int nt = 0; nt < 8; nt++)
#pragma unroll
            for (int q = 0; q < 4; q++) acc[mt][nt][q] = 0.f;

    const int NC = K / BK_;
    load_stage(0, 0);

    const int lr = lane & 15;
    const int lk = (lane >> 4) * 8;

    for (int c = 0; c < NC; c++) {
        if (c + 1 < NC) {
            load_stage((c + 1) & 1, (c + 1) * BK_);
            asm volatile("cp.async.wait_group 1;" ::: "memory");
        } else {
            asm volatile("cp.async.wait_group 0;" ::: "memory");
        }
        __syncthreads();

        const uint32_t so = sb + (uint32_t)((c & 1) * STG_E) * 2;
#pragma unroll
        for (int ks = 0; ks < 32; ks += 16) {
            uint32_t ahi[2][4], alo[2][4];
#pragma unroll
            for (int mt = 0; mt < 2; mt++) {
                uint32_t ad = so + (uint32_t)((wm * 32 + mt * 16 + lr) * PADK + ks + lk) * 2;
                ldmat_x4(ad, ahi[mt][0], ahi[mt][1], ahi[mt][2], ahi[mt][3]);
                ldmat_x4(ad + TILE_E * 2, alo[mt][0], alo[mt][1], alo[mt][2], alo[mt][3]);
            }
            uint32_t bhi[8][2], blo[8][2];
#pragma unroll
            for (int bt = 0; bt < 4; bt++) {
                uint32_t ad = so + (uint32_t)(2 * TILE_E) * 2 +
                              (uint32_t)((wn * 64 + bt * 16 + lr) * PADK + ks + lk) * 2;
                uint32_t r0, r1, r2, r3;
                ldmat_x4(ad, r0, r1, r2, r3);
                bhi[bt * 2][0] = r0; bhi[bt * 2][1] = r2;
                bhi[bt * 2 + 1][0] = r1; bhi[bt * 2 + 1][1] = r3;
                ldmat_x4(ad + TILE_E * 2, r0, r1, r2, r3);
                blo[bt * 2][0] = r0; blo[bt * 2][1] = r2;
                blo[bt * 2 + 1][0] = r1; blo[bt * 2 + 1][1] = r3;
            }
#pragma unroll
            for (int mt = 0; mt < 2; mt++)
#pragma unroll
                for (int nt = 0; nt < 8; nt++) {
                    mma16816(acc[mt][nt], ahi[mt], bhi[nt]);
                    mma16816(acc[mt][nt], ahi[mt], blo[nt]);
                    mma16816(acc[mt][nt], alo[mt], bhi[nt]);
                }
        }
        __syncthreads();
    }

    const int g = lane >> 2, t = lane & 3;
#pragma unroll
    for (int mt = 0; mt < 2; mt++) {
        const int r0 = m0 + wm * 32 + mt * 16 + g;
#pragma unroll
        for (int nt = 0; nt < 8; nt++) {
            const int col = n0 + wn * 64 + nt * 8 + 2 * t;
            float2 bv = *(const float2*)(bias + col);
            float v0 = acc[mt][nt][0] + bv.x, v1 = acc[mt][nt][1] + bv.y;
            float v2 = acc[mt][nt][2] + bv.x, v3 = acc[mt][nt][3] + bv.y;
            if (mode == 0) {
                *(float2*)(C + (size_t)r0 * N + col)       = make_float2(v0, v1);
                *(float2*)(C + (size_t)(r0 + 8) * N + col) = make_float2(v2, v3);
            } else {
                uint32_t h, l;
                split_pair(v0, v1, h, l);
                *(uint32_t*)(Chi + (size_t)r0 * N + col) = h;
                *(uint32_t*)(Clo + (size_t)r0 * N + col) = l;
                split_pair(v2, v3, h, l);
                *(uint32_t*)(Chi + (size_t)(r0 + 8) * N + col) = h;
                *(uint32_t*)(Clo + (size_t)(r0 + 8) * N + col) = l;
            }
        }
    }
}

// -------------------- tensor-core flash attention --------------------
// grid (S/128, H, B); 256 thr = 8 warps x 16 q-rows.
// smem: Qhi,Qlo + 2 stages x (Khi,Klo,Vhi,Vlo); rows padded to 72 bf16 (144B).
#define AP    72
#define AT    (128 * AP)                 // elems per component tile
#define ASMEM ((2 * AT + 8 * AT) * 2)    // 184320 bytes

#define SC_LOG2E 0.180336879f            // 0.125 * log2(e)
#define MASKED_U (-1442.69504f)          // -1000 * log2(e)

__global__ void __launch_bounds__(256, 1)
attn_mma(const __nv_bfloat16* __restrict__ qh_g, const __nv_bfloat16* __restrict__ ql_g,
         const int* __restrict__ mask,
         __nv_bfloat16* __restrict__ chi, __nv_bfloat16* __restrict__ clo)
{
    extern __shared__ __nv_bfloat16 sma[];
    const uint32_t sb = smem_u32(sma);
    const int tid  = threadIdx.x;
    const int lane = tid & 31;
    const int w    = tid >> 5;
    const int q0   = blockIdx.x * 128;
    const int h    = blockIdx.y;
    const int b    = blockIdx.z;
    const size_t rowbase = (size_t)b * S_;

    const int lr  = lane & 15;
    const int lkb = (lane >> 4) * 16;          // byte offset of k within row

    // ---- issue Q loads (hi+lo): 2048 chunks, 8 per thread ----
#pragma unroll
    for (int i = 0; i < 8; i++) {
        int c = tid + i * 256;
        int comp = c >> 10, idx = c & 1023;
        int row = idx >> 3, seg = idx & 7;
        const __nv_bfloat16* src = (comp ? ql_g : qh_g) +
            (rowbase + q0 + row) * N1_ + h * DH_ + seg * 8;
        cp_async16(sb + (uint32_t)(comp * AT + row * AP + seg * 8) * 2, src);
    }
    asm volatile("cp.async.commit_group;" ::: "memory");

    auto load_kv = [&](int kt, int st) {
#pragma unroll
        for (int i = 0; i < 16; i++) {
            int c = tid + i * 256;
            int tile = c >> 10, idx = c & 1023;
            int row = idx >> 3, seg = idx & 7;
            const __nv_bfloat16* base = (tile & 1) ? ql_g : qh_g;
            int coloff = (tile < 2) ? D_ : 2 * D_;   // K or V
            const __nv_bfloat16* src = base +
                (rowbase + kt * 128 + row) * N1_ + coloff + h * DH_ + seg * 8;
            cp_async16(sb + (uint32_t)(2 * AT + st * 4 * AT + tile * AT +
                                       row * AP + seg * 8) * 2, src);
        }
        asm volatile("cp.async.commit_group;" ::: "memory");
    };

    load_kv(0, 0);
    asm volatile("cp.async.wait_group 0;" ::: "memory");
    __syncthreads();

    // ---- preload Q fragments (4 k-steps, hi+lo) ----
    uint32_t qfh[4][4], qfl[4][4];
#pragma unroll
    for (int ks = 0; ks < 4; ks++) {
        uint32_t ad = sb + (uint32_t)((w * 16 + lr) * AP) * 2 + ks * 32 + lkb;
        ldmat_x4(ad, qfh[ks][0], qfh[ks][1], qfh[ks][2], qfh[ks][3]);
        ldmat_x4(ad + AT * 2, qfl[ks][0], qfl[ks][1], qfl[ks][2], qfl[ks][3]);
    }

    float o[8][4];
#pragma unroll
    for (int d = 0; d < 8; d++)
#pragma unroll
        for (int q = 0; q < 4; q++) o[d][q] = 0.f;
    float m0 = -1e30f, m1 = -1e30f, l0 = 0.f, l1 = 0.f;

    const int g  = lane >> 2;
    const int tq = lane & 3;
    const int r0g = q0 + w * 16 + g;
    const int lrow  = ((lane >> 3) & 1) * 8 + (lane & 7);  // V trans row lane
    const int lcolb = (lane >> 4) * 16;                    // V trans col byte

    for (int kt = 0; kt < S_ / 128; kt++) {
        if (kt > 0) {
            asm volatile("cp.async.wait_group 0;" ::: "memory");
        }
        __syncthreads();
        if (kt + 1 < S_ / 128) load_kv(kt + 1, (kt + 1) & 1);

        const uint32_t kvb = sb + (uint32_t)(2 * AT + (kt & 1) * 4 * AT) * 2;

        // ---- S = Q K^T (hi/lo 3-pass) ----
        float s[16][4];
#pragma unroll
        for (int nt = 0; nt < 16; nt++)
#pragma unroll
            for (int q = 0; q < 4; q++) s[nt][q] = 0.f;

#pragma unroll
        for (int ks = 0; ks < 4; ks++) {
#pragma unroll
            for (int bt = 0; bt < 8; bt++) {
                uint32_t ad = kvb + (uint32_t)((bt * 16 + lr) * AP) * 2 + ks * 32 + lkb;
                uint32_t h0, h1, h2, h3, e0, e1, e2, e3;
                ldmat_x4(ad, h0, h1, h2, h3);
                ldmat_x4(ad + AT * 2, e0, e1, e2, e3);
                uint32_t bhE[2] = {h0, h2}, bhO[2] = {h1, h3};
                uint32_t blE[2] = {e0, e2}, blO[2] = {e1, e3};
                mma16816(s[2 * bt],     qfh[ks], bhE);
                mma16816(s[2 * bt],     qfh[ks], blE);
                mma16816(s[2 * bt],     qfl[ks], bhE);
                mma16816(s[2 * bt + 1], qfh[ks], bhO);
                mma16816(s[2 * bt + 1], qfh[ks], blO);
                mma16816(s[2 * bt + 1], qfl[ks], bhO);
            }
        }

        // ---- scale + mask + online softmax (base-2) ----
        const int cb = kt * 128 + tq * 2;
        float mx0 = -1e30f, mx1 = -1e30f;
#pragma unroll
        for (int nt = 0; nt < 16; nt++) {
            int2 mv0 = __ldg((const int2*)(mask + (size_t)r0g * S_ + cb + nt * 8));
            int2 mv1 = __ldg((const int2*)(mask + (size_t)(r0g + 8) * S_ + cb + nt * 8));
            s[nt][0] = mv0.x ? s[nt][0] * SC_LOG2E : MASKED_U;
            s[nt][1] = mv0.y ? s[nt][1] * SC_LOG2E : MASKED_U;
            s[nt][2] = mv1.x ? s[nt][2] * SC_LOG2E : MASKED_U;
            s[nt][3] = mv1.y ? s[nt][3] * SC_LOG2E : MASKED_U;
            mx0 = fmaxf(mx0, fmaxf(s[nt][0], s[nt][1]));
            mx1 = fmaxf(mx1, fmaxf(s[nt][2], s[nt][3]));
        }
        mx0 = fmaxf(mx0, __shfl_xor_sync(0xffffffffu, mx0, 1));
        mx0 = fmaxf(mx0, __shfl_xor_sync(0xffffffffu, mx0, 2));
        mx1 = fmaxf(mx1, __shfl_xor_sync(0xffffffffu, mx1, 1));
        mx1 = fmaxf(mx1, __shfl_xor_sync(0xffffffffu, mx1, 2));
        const float mn0 = fmaxf(m0, mx0), mn1 = fmaxf(m1, mx1);
        const float c0 = ex2f(m0 - mn0), c1 = ex2f(m1 - mn1);
        m0 = mn0; m1 = mn1;
        float rs0 = 0.f, rs1 = 0.f;
#pragma unroll
        for (int nt = 0; nt < 16; nt++) {
            s[nt][0] = ex2f(s[nt][0] - mn0);
            s[nt][1] = ex2f(s[nt][1] - mn0);
            s[nt][2] = ex2f(s[nt][2] - mn1);
            s[nt][3] = ex2f(s[nt][3] - mn1);
            rs0 += s[nt][0] + s[nt][1];
            rs1 += s[nt][2] + s[nt][3];
        }
        l0 = l0 * c0 + rs0;
        l1 = l1 * c1 + rs1;
#pragma unroll
        for (int d = 0; d < 8; d++) {
            o[d][0] *= c0; o[d][1] *= c0; o[d][2] *= c1; o[d][3] *= c1;
        }

        // ---- O += P V (hi/lo 3-pass); P frags built in-register ----
        const uint32_t vb = kvb + (uint32_t)(2 * AT) * 2;
#pragma unroll
        for (int kk = 0; kk < 8; kk++) {
            uint32_t ph[4], pl[4];
            split_pair(s[2 * kk][0],     s[2 * kk][1],     ph[0], pl[0]);
            split_pair(s[2 * kk][2],     s[2 * kk][3],     ph[1], pl[1]);
            split_pair(s[2 * kk + 1][0], s[2 * kk + 1][1], ph[2], pl[2]);
            split_pair(s[2 * kk + 1][2], s[2 * kk + 1][3], ph[3], pl[3]);
#pragma unroll
            for (int nb = 0; nb < 4; nb++) {
                uint32_t ad = vb + (uint32_t)((kk * 16 + lrow) * AP) * 2 + nb * 32 + lcolb;
                uint32_t v0, v1, v2, v3, u0, u1, u2, u3;
                ldmat_x4t(ad, v0, v1, v2, v3);
                ldmat_x4t(ad + AT * 2, u0, u1, u2, u3);
                uint32_t bhE[2] = {v0, v1}, bhO[2] = {v2, v3};
                uint32_t blE[2] = {u0, u1}, blO[2] = {u2, u3};
                mma16816(o[2 * nb],     ph, bhE);
                mma16816(o[2 * nb],     ph, blE);
                mma16816(o[2 * nb],     pl, bhE);
                mma16816(o[2 * nb + 1], ph, bhO);
                mma16816(o[2 * nb + 1], ph, blO);
                mma16816(o[2 * nb + 1], pl, bhO);
            }
        }
    }

    // ---- epilogue: normalize, split, store ctx hi/lo ----
    l0 += __shfl_xor_sync(0xffffffffu, l0, 1);
    l0 += __shfl_xor_sync(0xffffffffu, l0, 2);
    l1 += __shfl_xor_sync(0xffffffffu, l1, 1);
    l1 += __shfl_xor_sync(0xffffffffu, l1, 2);
    const float i0 = 1.f / l0, i1 = 1.f / l1;
    const size_t ra = (rowbase + q0 + w * 16 + g) * D_ + h * DH_;
    const size_t rb = ra + 8 * D_;
#pragma unroll
    for (int d = 0; d < 8; d++) {
        const int col = d * 8 + tq * 2;
        uint32_t hp, lp;
        split_pair(o[d][0] * i0, o[d][1] * i0, hp, lp);
        *(uint32_t*)(chi + ra + col) = hp;
        *(uint32_t*)(clo + ra + col) = lp;
        split_pair(o[d][2] * i1, o[d][3] * i1, hp, lp);
        *(uint32_t*)(chi + rb + col) = hp;
        *(uint32_t*)(clo + rb + col) = lp;
    }
}

// -------------------- launch --------------------
extern "C" void kernel_launch(void* const* d_in, const int* in_sizes, int n_in,
                              void* d_out, int out_size)
{
    const float* x    = nullptr;
    const float* Wqkv = nullptr;
    const float* bqkv = nullptr;
    const float* Wout = nullptr;
    const float* bout = nullptr;
    const int*   mask = nullptr;

    for (int i = 0; i < n_in; i++) {
        long n = in_sizes[i];
        if      (n == (long)M_ * D_)   x    = (const float*)d_in[i];
        else if (n == (long)D_ * N1_)  Wqkv = (const float*)d_in[i];
        else if (n == (long)N1_)       bqkv = (const float*)d_in[i];
        else if (n == (long)D_ * D_)   Wout = (const float*)d_in[i];
        else if (n == (long)D_)        bout = (const float*)d_in[i];
        else if (n == (long)S_ * S_)   mask = (const int*)d_in[i];
    }

    __nv_bfloat16 *xhi, *xlo, *qkvhi, *qkvlo, *chi, *clo, *w1hi, *w1lo, *w2hi, *w2lo;
    cudaGetSymbolAddress((void**)&xhi, g_xhi);
    cudaGetSymbolAddress((void**)&xlo, g_xlo);
    cudaGetSymbolAddress((void**)&qkvhi, g_qkvhi);
    cudaGetSymbolAddress((void**)&qkvlo, g_qkvlo);
    cudaGetSymbolAddress((void**)&chi, g_chi);
    cudaGetSymbolAddress((void**)&clo, g_clo);
    cudaGetSymbolAddress((void**)&w1hi, g_w1hi);
    cudaGetSymbolAddress((void**)&w1lo, g_w1lo);
    cudaGetSymbolAddress((void**)&w2hi, g_w2hi);
    cudaGetSymbolAddress((void**)&w2lo, g_w2lo);

    cudaFuncSetAttribute(gemm_mma_split,
                         cudaFuncAttributeMaxDynamicSharedMemorySize, GSMEM);
    cudaFuncSetAttribute(attn_mma,
                         cudaFuncAttributeMaxDynamicSharedMemorySize, ASMEM);

    // prep
    split_kernel<<<(M_ * D_) / (256 * 4), 256>>>(x, xhi, xlo);
    transpose_split_kernel<<<dim3(N1_ / 32, D_ / 32), dim3(32, 8)>>>(Wqkv, w1hi, w1lo, D_, N1_);
    transpose_split_kernel<<<dim3(D_ / 32, D_ / 32), dim3(32, 8)>>>(Wout, w2hi, w2lo, D_, D_);

    // qkv = x @ Wqkv + b  (split bf16 out)
    gemm_mma_split<<<dim3(N1_ / 128, M_ / 128), 256, GSMEM>>>(
        xhi, xlo, w1hi, w1lo, bqkv, nullptr, qkvhi, qkvlo, N1_, D_, 1);

    // attention (split bf16 ctx out)
    attn_mma<<<dim3(S_ / 128, H_, B_), 256, ASMEM>>>(qkvhi, qkvlo, mask, chi, clo);

    // out = ctx @ Wout + b  (fp32 out)
    gemm_mma_split<<<dim3(D_ / 128, M_ / 128), 256, GSMEM>>>(
        chi, clo, w2hi, w2lo, bout, (float*)d_out, nullptr, nullptr, D_, D_, 0);
}

// round 5
// speedup vs baseline: 2.6186x; 1.0603x over previous
#include <cuda_runtime.h>
#include <cuda_bf16.h>
#include <cstdint>

// Problem constants
#define B_   4
#define S_   2048
#define D_   1024
#define H_   16
#define DH_  64
#define M_   (B_ * S_)      // 8192
#define N1_  (3 * D_)       // 3072

// -------------------- scratch --------------------
__device__ __nv_bfloat16 g_xhi[(size_t)M_ * D_];
__device__ __nv_bfloat16 g_xlo[(size_t)M_ * D_];
__device__ __nv_bfloat16 g_qkvhi[(size_t)M_ * N1_];
__device__ __nv_bfloat16 g_qkvlo[(size_t)M_ * N1_];
__device__ __nv_bfloat16 g_chi[(size_t)M_ * D_];
__device__ __nv_bfloat16 g_clo[(size_t)M_ * D_];
__device__ __nv_bfloat16 g_w1hi[(size_t)N1_ * D_];
__device__ __nv_bfloat16 g_w1lo[(size_t)N1_ * D_];
__device__ __nv_bfloat16 g_w2hi[(size_t)D_ * D_];
__device__ __nv_bfloat16 g_w2lo[(size_t)D_ * D_];

// -------------------- helpers --------------------
__device__ __forceinline__ uint32_t smem_u32(const void* p) {
    uint32_t a;
    asm("{ .reg .u64 t; cvta.to.shared.u64 t, %1; cvt.u32.u64 %0, t; }"
        : "=r"(a) : "l"(p));
    return a;
}
__device__ __forceinline__ void cp_async16(uint32_t dst, const void* src) {
    asm volatile("cp.async.cg.shared.global [%0], [%1], 16;"
                 :: "r"(dst), "l"(src) : "memory");
}
__device__ __forceinline__ void ldmat_x4(uint32_t addr, uint32_t& r0, uint32_t& r1,
                                         uint32_t& r2, uint32_t& r3) {
    asm volatile("ldmatrix.sync.aligned.m8n8.x4.shared.b16 {%0,%1,%2,%3}, [%4];"
                 : "=r"(r0), "=r"(r1), "=r"(r2), "=r"(r3) : "r"(addr));
}
__device__ __forceinline__ void ldmat_x4t(uint32_t addr, uint32_t& r0, uint32_t& r1,
                                          uint32_t& r2, uint32_t& r3) {
    asm volatile("ldmatrix.sync.aligned.m8n8.x4.trans.shared.b16 {%0,%1,%2,%3}, [%4];"
                 : "=r"(r0), "=r"(r1), "=r"(r2), "=r"(r3) : "r"(addr));
}
__device__ __forceinline__ void mma16816(float* c, const uint32_t* a,
                                         const uint32_t* b) {
    asm volatile(
        "mma.sync.aligned.m16n8k16.row.col.f32.bf16.bf16.f32 "
        "{%0,%1,%2,%3}, {%4,%5,%6,%7}, {%8,%9}, {%0,%1,%2,%3};"
        : "+f"(c[0]), "+f"(c[1]), "+f"(c[2]), "+f"(c[3])
        : "r"(a[0]), "r"(a[1]), "r"(a[2]), "r"(a[3]), "r"(b[0]), "r"(b[1]));
}
__device__ __forceinline__ float ex2f(float x) {
    float y;
    asm("ex2.approx.ftz.f32 %0, %1;" : "=f"(y) : "f"(x));
    return y;
}
__device__ __forceinline__ uint32_t pack_bf2(float lo, float hi) {
    uint32_t d;
    asm("cvt.rn.bf16x2.f32 %0, %1, %2;" : "=r"(d) : "f"(hi), "f"(lo));
    return d;
}
__device__ __forceinline__ void split_pair(float a0, float a1,
                                           uint32_t& ph, uint32_t& pl) {
    ph = pack_bf2(a0, a1);
    float h0 = __uint_as_float(ph << 16);
    float h1 = __uint_as_float(ph & 0xFFFF0000u);
    pl = pack_bf2(a0 - h0, a1 - h1);
}
__device__ __forceinline__ void split1(float x, __nv_bfloat16& h, __nv_bfloat16& l) {
    h = __float2bfloat16(x);
    l = __float2bfloat16(x - __bfloat162float(h));
}

// -------------------- split / transpose prep kernels --------------------
__global__ void __launch_bounds__(256)
split_kernel(const float* __restrict__ in, __nv_bfloat16* __restrict__ hi,
             __nv_bfloat16* __restrict__ lo)
{
    int i = (blockIdx.x * 256 + threadIdx.x) * 4;
    float4 v = *(const float4*)(in + i);
    union { __nv_bfloat16 b[4]; uint2 u; } H, L;
    split1(v.x, H.b[0], L.b[0]);
    split1(v.y, H.b[1], L.b[1]);
    split1(v.z, H.b[2], L.b[2]);
    split1(v.w, H.b[3], L.b[3]);
    *(uint2*)(hi + i) = H.u;
    *(uint2*)(lo + i) = L.u;
}

__global__ void __launch_bounds__(256)
transpose_split_kernel(const float* __restrict__ W, __nv_bfloat16* __restrict__ hi,
                       __nv_bfloat16* __restrict__ lo, int K, int N)
{
    __shared__ float t[32][33];
    const int n0 = blockIdx.x * 32, k0 = blockIdx.y * 32;
    const int tx = threadIdx.x, ty = threadIdx.y;
#pragma unroll
    for (int i = ty; i < 32; i += 8)
        t[i][tx] = W[(size_t)(k0 + i) * N + n0 + tx];
    __syncthreads();
#pragma unroll
    for (int i = ty; i < 32; i += 8) {
        float x = t[tx][i];
        __nv_bfloat16 h, l;
        split1(x, h, l);
        size_t o = (size_t)(n0 + i) * K + k0 + tx;
        hi[o] = h; lo[o] = l;
    }
}

// -------------------- bf16-split GEMM (mma.sync, swizzled smem, 3-stage) ------
// C[M,N] = (Ahi+Alo) @ (Bhi+Blo)^T + bias,  B stored [N,K] K-major.
// 128x128 block tile, BK=32, 8 warps (4M x 2N, 32x64 warp tiles).
// smem row = 64 B (32 bf16), XOR swizzle: seg' = seg ^ ((row>>1)&3).
#define GTILE_B 8192u                   // 128 rows * 64 B
#define GSTG_B  (4u * GTILE_B)          // 32768 per stage (Ahi,Alo,Bhi,Blo)
#define GSMEM   (3u * GSTG_B)           // 98304 bytes, 3 stages

__device__ __forceinline__ uint32_t gsw(int row, int seg) {
    return (uint32_t)(row * 64 + ((seg ^ ((row >> 1) & 3)) << 4));
}

__global__ void __launch_bounds__(256, 2)
gemm_mma_split(const __nv_bfloat16* __restrict__ Ahi, const __nv_bfloat16* __restrict__ Alo,
               const __nv_bfloat16* __restrict__ Bhi, const __nv_bfloat16* __restrict__ Blo,
               const float* __restrict__ bias, float* __restrict__ C,
               __nv_bfloat16* __restrict__ Chi, __nv_bfloat16* __restrict__ Clo,
               int N, int K, int mode)
{
    extern __shared__ __nv_bfloat16 smb[];
    const uint32_t sb = smem_u32(smb);
    const int tid  = threadIdx.x;
    const int lane = tid & 31;
    const int wid  = tid >> 5;
    const int wm   = wid & 3;
    const int wn   = wid >> 2;
    const int m0   = blockIdx.y * 128;
    const int n0   = blockIdx.x * 128;

    // per-thread fixed load slot: 2048 16B chunks/stage, 8 per thread
    auto load_stage = [&](int st, int k0) {
#pragma unroll
        for (int i = 0; i < 8; i++) {
            int c    = tid + i * 256;
            int tile = c >> 9;           // 0:Ahi 1:Alo 2:Bhi 3:Blo
            int idx  = c & 511;
            int row  = idx >> 2;
            int seg  = idx & 3;
            const __nv_bfloat16* src;
            if      (tile == 0) src = Ahi + (size_t)(m0 + row) * K + k0 + seg * 8;
            else if (tile == 1) src = Alo + (size_t)(m0 + row) * K + k0 + seg * 8;
            else if (tile == 2) src = Bhi + (size_t)(n0 + row) * K + k0 + seg * 8;
            else                src = Blo + (size_t)(n0 + row) * K + k0 + seg * 8;
            cp_async16(sb + (uint32_t)st * GSTG_B + (uint32_t)tile * GTILE_B +
                       gsw(row, seg), src);
        }
        asm volatile("cp.async.commit_group;" ::: "memory");
    };

    float acc[2][8][4];
#pragma unroll
    for (int mt = 0; mt < 2; mt++)
#pragma unroll
        for (int nt = 0; nt < 8; nt++)
#pragma unroll
            for (int q = 0; q < 4; q++) acc[mt][nt][q] = 0.f;

    const int NC = K / 32;
    load_stage(0, 0);
    load_stage(1, 32);

    const int lr = lane & 15;
    const int lk = (lane >> 4) * 8;      // elem offset within 16-K step

    int stage = 0;
    for (int c = 0; c < NC; c++) {
        asm volatile("cp.async.wait_group 1;" ::: "memory");
        __syncthreads();
        if (c + 2 < NC) {
            int st2 = stage + 2; if (st2 >= 3) st2 -= 3;
            load_stage(st2, (c + 2) * 32);
        } else {
            asm volatile("cp.async.commit_group;" ::: "memory"); // keep group count
        }

        const uint32_t so = sb + (uint32_t)stage * GSTG_B;
#pragma unroll
        for (int ks = 0; ks < 32; ks += 16) {
            uint32_t ahi[2][4], alo[2][4];
#pragma unroll
            for (int mt = 0; mt < 2; mt++) {
                int row = wm * 32 + mt * 16 + lr;
                int s   = (ks + lk) >> 3;
                uint32_t ad = so + gsw(row, s);
                ldmat_x4(ad, ahi[mt][0], ahi[mt][1], ahi[mt][2], ahi[mt][3]);
                ldmat_x4(ad + GTILE_B, alo[mt][0], alo[mt][1], alo[mt][2], alo[mt][3]);
            }
            uint32_t bhi[8][2], blo[8][2];
#pragma unroll
            for (int bt = 0; bt < 4; bt++) {
                int row = wn * 64 + bt * 16 + lr;
                int s   = (ks + lk) >> 3;
                uint32_t ad = so + 2 * GTILE_B + gsw(row, s);
                uint32_t r0, r1, r2, r3;
                ldmat_x4(ad, r0, r1, r2, r3);
                bhi[bt * 2][0] = r0; bhi[bt * 2][1] = r2;
                bhi[bt * 2 + 1][0] = r1; bhi[bt * 2 + 1][1] = r3;
                ldmat_x4(ad + GTILE_B, r0, r1, r2, r3);
                blo[bt * 2][0] = r0; blo[bt * 2][1] = r2;
                blo[bt * 2 + 1][0] = r1; blo[bt * 2 + 1][1] = r3;
            }
#pragma unroll
            for (int mt = 0; mt < 2; mt++)
#pragma unroll
                for (int nt = 0; nt < 8; nt++) {
                    mma16816(acc[mt][nt], ahi[mt], bhi[nt]);
                    mma16816(acc[mt][nt], ahi[mt], blo[nt]);
                    mma16816(acc[mt][nt], alo[mt], bhi[nt]);
                }
        }
        if (++stage >= 3) stage = 0;
    }

    const int g = lane >> 2, t = lane & 3;
#pragma unroll
    for (int mt = 0; mt < 2; mt++) {
        const int r0 = m0 + wm * 32 + mt * 16 + g;
#pragma unroll
        for (int nt = 0; nt < 8; nt++) {
            const int col = n0 + wn * 64 + nt * 8 + 2 * t;
            float2 bv = *(const float2*)(bias + col);
            float v0 = acc[mt][nt][0] + bv.x, v1 = acc[mt][nt][1] + bv.y;
            float v2 = acc[mt][nt][2] + bv.x, v3 = acc[mt][nt][3] + bv.y;
            if (mode == 0) {
                *(float2*)(C + (size_t)r0 * N + col)       = make_float2(v0, v1);
                *(float2*)(C + (size_t)(r0 + 8) * N + col) = make_float2(v2, v3);
            } else {
                uint32_t h, l;
                split_pair(v0, v1, h, l);
                *(uint32_t*)(Chi + (size_t)r0 * N + col) = h;
                *(uint32_t*)(Clo + (size_t)r0 * N + col) = l;
                split_pair(v2, v3, h, l);
                *(uint32_t*)(Chi + (size_t)(r0 + 8) * N + col) = h;
                *(uint32_t*)(Clo + (size_t)(r0 + 8) * N + col) = l;
            }
        }
    }
}

// -------------------- tensor-core flash attention --------------------
// grid (S/128, H, B); 256 thr = 8 warps x 16 q-rows.
// smem: Qhi,Qlo + 2 stages x (Khi,Klo,Vhi,Vlo); rows padded to 72 bf16 (144B).
#define AP    72
#define AT    (128 * AP)
#define ASMEM ((2 * AT + 8 * AT) * 2)    // 184320 bytes

#define SC_LOG2E 0.180336879f            // 0.125 * log2(e)
#define MASKED_U (-1442.69504f)          // -1000 * log2(e)

__global__ void __launch_bounds__(256, 1)
attn_mma(const __nv_bfloat16* __restrict__ qh_g, const __nv_bfloat16* __restrict__ ql_g,
         const int* __restrict__ mask,
         __nv_bfloat16* __restrict__ chi, __nv_bfloat16* __restrict__ clo)
{
    extern __shared__ __nv_bfloat16 sma[];
    const uint32_t sb = smem_u32(sma);
    const int tid  = threadIdx.x;
    const int lane = tid & 31;
    const int w    = tid >> 5;
    const int q0   = blockIdx.x * 128;
    const int h    = blockIdx.y;
    const int b    = blockIdx.z;
    const size_t rowbase = (size_t)b * S_;

    const int lr  = lane & 15;
    const int lkb = (lane >> 4) * 16;

    // Q loads (hi+lo)
#pragma unroll
    for (int i = 0; i < 8; i++) {
        int c = tid + i * 256;
        int comp = c >> 10, idx = c & 1023;
        int row = idx >> 3, seg = idx & 7;
        const __nv_bfloat16* src = (comp ? ql_g : qh_g) +
            (rowbase + q0 + row) * N1_ + h * DH_ + seg * 8;
        cp_async16(sb + (uint32_t)(comp * AT + row * AP + seg * 8) * 2, src);
    }
    asm volatile("cp.async.commit_group;" ::: "memory");

    auto load_kv = [&](int kt, int st) {
#pragma unroll
        for (int i = 0; i < 16; i++) {
            int c = tid + i * 256;
            int tile = c >> 10, idx = c & 1023;
            int row = idx >> 3, seg = idx & 7;
            const __nv_bfloat16* base = (tile & 1) ? ql_g : qh_g;
            int coloff = (tile < 2) ? D_ : 2 * D_;
            const __nv_bfloat16* src = base +
                (rowbase + kt * 128 + row) * N1_ + coloff + h * DH_ + seg * 8;
            cp_async16(sb + (uint32_t)(2 * AT + st * 4 * AT + tile * AT +
                                       row * AP + seg * 8) * 2, src);
        }
        asm volatile("cp.async.commit_group;" ::: "memory");
    };

    load_kv(0, 0);
    asm volatile("cp.async.wait_group 0;" ::: "memory");
    __syncthreads();

    // preload Q fragments
    uint32_t qfh[4][4], qfl[4][4];
#pragma unroll
    for (int ks = 0; ks < 4; ks++) {
        uint32_t ad = sb + (uint32_t)((w * 16 + lr) * AP) * 2 + ks * 32 + lkb;
        ldmat_x4(ad, qfh[ks][0], qfh[ks][1], qfh[ks][2], qfh[ks][3]);
        ldmat_x4(ad + AT * 2, qfl[ks][0], qfl[ks][1], qfl[ks][2], qfl[ks][3]);
    }

    float o[8][4];
#pragma unroll
    for (int d = 0; d < 8; d++)
#pragma unroll
        for (int q = 0; q < 4; q++) o[d][q] = 0.f;
    float m0 = -1e30f, m1 = -1e30f, l0 = 0.f, l1 = 0.f;

    const int g  = lane >> 2;
    const int tq = lane & 3;
    const int r0g = q0 + w * 16 + g;
    const int lrow  = ((lane >> 3) & 1) * 8 + (lane & 7);
    const int lcolb = (lane >> 4) * 16;

    for (int kt = 0; kt < S_ / 128; kt++) {
        if (kt > 0) {
            asm volatile("cp.async.wait_group 0;" ::: "memory");
        }
        __syncthreads();
        if (kt + 1 < S_ / 128) load_kv(kt + 1, (kt + 1) & 1);

        const uint32_t kvb = sb + (uint32_t)(2 * AT + (kt & 1) * 4 * AT) * 2;

        // ---- S = Q K^T, software-pipelined over flattened (ks,bt) ----
        float s[16][4];
#pragma unroll
        for (int nt = 0; nt < 16; nt++)
#pragma unroll
            for (int q = 0; q < 4; q++) s[nt][q] = 0.f;

        uint32_t kf[2][4], ef[2][4];
        {
            uint32_t ad = kvb + (uint32_t)(lr * AP) * 2 + lkb;  // ks=0, bt=0
            ldmat_x4(ad, kf[0][0], kf[0][1], kf[0][2], kf[0][3]);
            ldmat_x4(ad + AT * 2, ef[0][0], ef[0][1], ef[0][2], ef[0][3]);
        }
#pragma unroll
        for (int idx = 0; idx < 32; idx++) {
            const int ks = idx >> 3, bt = idx & 7;
            const int cur = idx & 1, nxt = cur ^ 1;
            if (idx < 31) {
                const int ks2 = (idx + 1) >> 3, bt2 = (idx + 1) & 7;
                uint32_t ad = kvb + (uint32_t)((bt2 * 16 + lr) * AP) * 2 + ks2 * 32 + lkb;
                ldmat_x4(ad, kf[nxt][0], kf[nxt][1], kf[nxt][2], kf[nxt][3]);
                ldmat_x4(ad + AT * 2, ef[nxt][0], ef[nxt][1], ef[nxt][2], ef[nxt][3]);
            }
            uint32_t bhE[2] = {kf[cur][0], kf[cur][2]}, bhO[2] = {kf[cur][1], kf[cur][3]};
            uint32_t blE[2] = {ef[cur][0], ef[cur][2]}, blO[2] = {ef[cur][1], ef[cur][3]};
            mma16816(s[2 * bt],     qfh[ks], bhE);
            mma16816(s[2 * bt],     qfh[ks], blE);
            mma16816(s[2 * bt],     qfl[ks], bhE);
            mma16816(s[2 * bt + 1], qfh[ks], bhO);
            mma16816(s[2 * bt + 1], qfh[ks], blO);
            mma16816(s[2 * bt + 1], qfl[ks], bhO);
        }

        // ---- scale + mask + online softmax (base-2) ----
        const int cb = kt * 128 + tq * 2;
        float mx0 = -1e30f, mx1 = -1e30f;
#pragma unroll
        for (int nt = 0; nt < 16; nt++) {
            int2 mv0 = __ldg((const int2*)(mask + (size_t)r0g * S_ + cb + nt * 8));
            int2 mv1 = __ldg((const int2*)(mask + (size_t)(r0g + 8) * S_ + cb + nt * 8));
            s[nt][0] = mv0.x ? s[nt][0] * SC_LOG2E : MASKED_U;
            s[nt][1] = mv0.y ? s[nt][1] * SC_LOG2E : MASKED_U;
            s[nt][2] = mv1.x ? s[nt][2] * SC_LOG2E : MASKED_U;
            s[nt][3] = mv1.y ? s[nt][3] * SC_LOG2E : MASKED_U;
            mx0 = fmaxf(mx0, fmaxf(s[nt][0], s[nt][1]));
            mx1 = fmaxf(mx1, fmaxf(s[nt][2], s[nt][3]));
        }
        mx0 = fmaxf(mx0, __shfl_xor_sync(0xffffffffu, mx0, 1));
        mx0 = fmaxf(mx0, __shfl_xor_sync(0xffffffffu, mx0, 2));
        mx1 = fmaxf(mx1, __shfl_xor_sync(0xffffffffu, mx1, 1));
        mx1 = fmaxf(mx1, __shfl_xor_sync(0xffffffffu, mx1, 2));
        const float mn0 = fmaxf(m0, mx0), mn1 = fmaxf(m1, mx1);
        const float c0 = ex2f(m0 - mn0), c1 = ex2f(m1 - mn1);
        m0 = mn0; m1 = mn1;
        float rs0 = 0.f, rs1 = 0.f;
#pragma unroll
        for (int nt = 0; nt < 16; nt++) {
            s[nt][0] = ex2f(s[nt][0] - mn0);
            s[nt][1] = ex2f(s[nt][1] - mn0);
            s[nt][2] = ex2f(s[nt][2] - mn1);
            s[nt][3] = ex2f(s[nt][3] - mn1);
            rs0 += s[nt][0] + s[nt][1];
            rs1 += s[nt][2] + s[nt][3];
        }
        l0 = l0 * c0 + rs0;
        l1 = l1 * c1 + rs1;
#pragma unroll
        for (int d = 0; d < 8; d++) {
            o[d][0] *= c0; o[d][1] *= c0; o[d][2] *= c1; o[d][3] *= c1;
        }

        // ---- O += P V, software-pipelined over flattened (kk,nb) ----
        const uint32_t vb = kvb + (uint32_t)(2 * AT) * 2;
        uint32_t vf[2][4], uf[2][4];
        {
            uint32_t ad = vb + (uint32_t)(lrow * AP) * 2 + lcolb;  // kk=0, nb=0
            ldmat_x4t(ad, vf[0][0], vf[0][1], vf[0][2], vf[0][3]);
            ldmat_x4t(ad + AT * 2, uf[0][0], uf[0][1], uf[0][2], uf[0][3]);
        }
        uint32_t ph[4], pl[4];
#pragma unroll
        for (int idx = 0; idx < 32; idx++) {
            const int kk = idx >> 2, nb = idx & 3;
            const int cur = idx & 1, nxt = cur ^ 1;
            if (nb == 0) {
                split_pair(s[2 * kk][0],     s[2 * kk][1],     ph[0], pl[0]);
                split_pair(s[2 * kk][2],     s[2 * kk][3],     ph[1], pl[1]);
                split_pair(s[2 * kk + 1][0], s[2 * kk + 1][1], ph[2], pl[2]);
                split_pair(s[2 * kk + 1][2], s[2 * kk + 1][3], ph[3], pl[3]);
            }
            if (idx < 31) {
                const int kk2 = (idx + 1) >> 2, nb2 = (idx + 1) & 3;
                uint32_t ad = vb + (uint32_t)((kk2 * 16 + lrow) * AP) * 2 + nb2 * 32 + lcolb;
                ldmat_x4t(ad, vf[nxt][0], vf[nxt][1], vf[nxt][2], vf[nxt][3]);
                ldmat_x4t(ad + AT * 2, uf[nxt][0], uf[nxt][1], uf[nxt][2], uf[nxt][3]);
            }
            uint32_t bhE[2] = {vf[cur][0], vf[cur][1]}, bhO[2] = {vf[cur][2], vf[cur][3]};
            uint32_t blE[2] = {uf[cur][0], uf[cur][1]}, blO[2] = {uf[cur][2], uf[cur][3]};
            mma16816(o[2 * nb],     ph, bhE);
            mma16816(o[2 * nb],     ph, blE);
            mma16816(o[2 * nb],     pl, bhE);
            mma16816(o[2 * nb + 1], ph, bhO);
            mma16816(o[2 * nb + 1], ph, blO);
            mma16816(o[2 * nb + 1], pl, bhO);
        }
    }

    // ---- epilogue ----
    l0 += __shfl_xor_sync(0xffffffffu, l0, 1);
    l0 += __shfl_xor_sync(0xffffffffu, l0, 2);
    l1 += __shfl_xor_sync(0xffffffffu, l1, 1);
    l1 += __shfl_xor_sync(0xffffffffu, l1, 2);
    const float i0 = 1.f / l0, i1 = 1.f / l1;
    const size_t ra = (rowbase + q0 + w * 16 + g) * D_ + h * DH_;
    const size_t rb = ra + 8 * D_;
#pragma unroll
    for (int d = 0; d < 8; d++) {
        const int col = d * 8 + tq * 2;
        uint32_t hp, lp;
        split_pair(o[d][0] * i0, o[d][1] * i0, hp, lp);
        *(uint32_t*)(chi + ra + col) = hp;
        *(uint32_t*)(clo + ra + col) = lp;
        split_pair(o[d][2] * i1, o[d][3] * i1, hp, lp);
        *(uint32_t*)(chi + rb + col) = hp;
        *(uint32_t*)(clo + rb + col) = lp;
    }
}

// -------------------- launch --------------------
extern "C" void kernel_launch(void* const* d_in, const int* in_sizes, int n_in,
                              void* d_out, int out_size)
{
    const float* x    = nullptr;
    const float* Wqkv = nullptr;
    const float* bqkv = nullptr;
    const float* Wout = nullptr;
    const float* bout = nullptr;
    const int*   mask = nullptr;

    for (int i = 0; i < n_in; i++) {
        long n = in_sizes[i];
        if      (n == (long)M_ * D_)   x    = (const float*)d_in[i];
        else if (n == (long)D_ * N1_)  Wqkv = (const float*)d_in[i];
        else if (n == (long)N1_)       bqkv = (const float*)d_in[i];
        else if (n == (long)D_ * D_)   Wout = (const float*)d_in[i];
        else if (n == (long)D_)        bout = (const float*)d_in[i];
        else if (n == (long)S_ * S_)   mask = (const int*)d_in[i];
    }

    __nv_bfloat16 *xhi, *xlo, *qkvhi, *qkvlo, *chi, *clo, *w1hi, *w1lo, *w2hi, *w2lo;
    cudaGetSymbolAddress((void**)&xhi, g_xhi);
    cudaGetSymbolAddress((void**)&xlo, g_xlo);
    cudaGetSymbolAddress((void**)&qkvhi, g_qkvhi);
    cudaGetSymbolAddress((void**)&qkvlo, g_qkvlo);
    cudaGetSymbolAddress((void**)&chi, g_chi);
    cudaGetSymbolAddress((void**)&clo, g_clo);
    cudaGetSymbolAddress((void**)&w1hi, g_w1hi);
    cudaGetSymbolAddress((void**)&w1lo, g_w1lo);
    cudaGetSymbolAddress((void**)&w2hi, g_w2hi);
    cudaGetSymbolAddress((void**)&w2lo, g_w2lo);

    cudaFuncSetAttribute(gemm_mma_split,
                         cudaFuncAttributeMaxDynamicSharedMemorySize, GSMEM);
    cudaFuncSetAttribute(attn_mma,
                         cudaFuncAttributeMaxDynamicSharedMemorySize, ASMEM);

    split_kernel<<<(M_ * D_) / (256 * 4), 256>>>(x, xhi, xlo);
    transpose_split_kernel<<<dim3(N1_ / 32, D_ / 32), dim3(32, 8)>>>(Wqkv, w1hi, w1lo, D_, N1_);
    transpose_split_kernel<<<dim3(D_ / 32, D_ / 32), dim3(32, 8)>>>(Wout, w2hi, w2lo, D_, D_);

    gemm_mma_split<<<dim3(N1_ / 128, M_ / 128), 256, GSMEM>>>(
        xhi, xlo, w1hi, w1lo, bqkv, nullptr, qkvhi, qkvlo, N1_, D_, 1);

    attn_mma<<<dim3(S_ / 128, H_, B_), 256, ASMEM>>>(qkvhi, qkvlo, mask, chi, clo);

    gemm_mma_split<<<dim3(D_ / 128, M_ / 128), 256, GSMEM>>>(
        chi, clo, w2hi, w2lo, bout, (float*)d_out, nullptr, nullptr, D_, D_, 0);
}

// round 6
// speedup vs baseline: 2.8062x; 1.0717x over previous
#include <cuda_runtime.h>
#include <cuda_bf16.h>
#include <cstdint>

// Problem constants
#define B_   4
#define S_   2048
#define D_   1024
#define H_   16
#define DH_  64
#define M_   (B_ * S_)      // 8192
#define N1_  (3 * D_)       // 3072

// -------------------- scratch --------------------
__device__ __nv_bfloat16 g_xhi[(size_t)M_ * D_];
__device__ __nv_bfloat16 g_xlo[(size_t)M_ * D_];
__device__ __nv_bfloat16 g_qkvhi[(size_t)M_ * N1_];
__device__ __nv_bfloat16 g_qkvlo[(size_t)M_ * N1_];
__device__ __nv_bfloat16 g_chi[(size_t)M_ * D_];
__device__ __nv_bfloat16 g_clo[(size_t)M_ * D_];
__device__ __nv_bfloat16 g_w1hi[(size_t)N1_ * D_];
__device__ __nv_bfloat16 g_w1lo[(size_t)N1_ * D_];
__device__ __nv_bfloat16 g_w2hi[(size_t)D_ * D_];
__device__ __nv_bfloat16 g_w2lo[(size_t)D_ * D_];

// -------------------- helpers --------------------
__device__ __forceinline__ uint32_t smem_u32(const void* p) {
    uint32_t a;
    asm("{ .reg .u64 t; cvta.to.shared.u64 t, %1; cvt.u32.u64 %0, t; }"
        : "=r"(a) : "l"(p));
    return a;
}
__device__ __forceinline__ void cp_async16(uint32_t dst, const void* src) {
    asm volatile("cp.async.cg.shared.global [%0], [%1], 16;"
                 :: "r"(dst), "l"(src) : "memory");
}
__device__ __forceinline__ void ldmat_x4(uint32_t addr, uint32_t& r0, uint32_t& r1,
                                         uint32_t& r2, uint32_t& r3) {
    asm volatile("ldmatrix.sync.aligned.m8n8.x4.shared.b16 {%0,%1,%2,%3}, [%4];"
                 : "=r"(r0), "=r"(r1), "=r"(r2), "=r"(r3) : "r"(addr));
}
__device__ __forceinline__ void ldmat_x4t(uint32_t addr, uint32_t& r0, uint32_t& r1,
                                          uint32_t& r2, uint32_t& r3) {
    asm volatile("ldmatrix.sync.aligned.m8n8.x4.trans.shared.b16 {%0,%1,%2,%3}, [%4];"
                 : "=r"(r0), "=r"(r1), "=r"(r2), "=r"(r3) : "r"(addr));
}
__device__ __forceinline__ void mma16816(float* c, const uint32_t* a,
                                         const uint32_t* b) {
    asm volatile(
        "mma.sync.aligned.m16n8k16.row.col.f32.bf16.bf16.f32 "
        "{%0,%1,%2,%3}, {%4,%5,%6,%7}, {%8,%9}, {%0,%1,%2,%3};"
        : "+f"(c[0]), "+f"(c[1]), "+f"(c[2]), "+f"(c[3])
        : "r"(a[0]), "r"(a[1]), "r"(a[2]), "r"(a[3]), "r"(b[0]), "r"(b[1]));
}
__device__ __forceinline__ float ex2f(float x) {
    float y;
    asm("ex2.approx.ftz.f32 %0, %1;" : "=f"(y) : "f"(x));
    return y;
}
__device__ __forceinline__ uint32_t pack_bf2(float lo, float hi) {
    uint32_t d;
    asm("cvt.rn.bf16x2.f32 %0, %1, %2;" : "=r"(d) : "f"(hi), "f"(lo));
    return d;
}
__device__ __forceinline__ void split_pair(float a0, float a1,
                                           uint32_t& ph, uint32_t& pl) {
    ph = pack_bf2(a0, a1);
    float h0 = __uint_as_float(ph << 16);
    float h1 = __uint_as_float(ph & 0xFFFF0000u);
    pl = pack_bf2(a0 - h0, a1 - h1);
}
__device__ __forceinline__ void split1(float x, __nv_bfloat16& h, __nv_bfloat16& l) {
    h = __float2bfloat16(x);
    l = __float2bfloat16(x - __bfloat162float(h));
}

// -------------------- prep kernels --------------------
__global__ void __launch_bounds__(256)
split_kernel(const float* __restrict__ in, __nv_bfloat16* __restrict__ hi,
             __nv_bfloat16* __restrict__ lo)
{
    int i = (blockIdx.x * 256 + threadIdx.x) * 4;
    float4 v = *(const float4*)(in + i);
    union { __nv_bfloat16 b[4]; uint2 u; } H, L;
    split1(v.x, H.b[0], L.b[0]);
    split1(v.y, H.b[1], L.b[1]);
    split1(v.z, H.b[2], L.b[2]);
    split1(v.w, H.b[3], L.b[3]);
    *(uint2*)(hi + i) = H.u;
    *(uint2*)(lo + i) = L.u;
}

__global__ void __launch_bounds__(256)
transpose_split_kernel(const float* __restrict__ W, __nv_bfloat16* __restrict__ hi,
                       __nv_bfloat16* __restrict__ lo, int K, int N)
{
    __shared__ float t[32][33];
    const int n0 = blockIdx.x * 32, k0 = blockIdx.y * 32;
    const int tx = threadIdx.x, ty = threadIdx.y;
#pragma unroll
    for (int i = ty; i < 32; i += 8)
        t[i][tx] = W[(size_t)(k0 + i) * N + n0 + tx];
    __syncthreads();
#pragma unroll
    for (int i = ty; i < 32; i += 8) {
        float x = t[tx][i];
        __nv_bfloat16 h, l;
        split1(x, h, l);
        size_t o = (size_t)(n0 + i) * K + k0 + tx;
        hi[o] = h; lo[o] = l;
    }
}

// -------------------- bf16-split GEMM (mma.sync, K=1024 fixed) --------------------
#define GK      1024
#define GNC     (GK / 32)               // 32 k-chunks
#define GTILE_B 8192u
#define GSTG_B  (4u * GTILE_B)
#define GSMEM   (3u * GSTG_B)           // 98304

__device__ __forceinline__ uint32_t gsw(int row, int seg) {
    return (uint32_t)(row * 64 + ((seg ^ ((row >> 1) & 3)) << 4));
}

__global__ void __launch_bounds__(256, 2)
gemm_mma_split(const __nv_bfloat16* __restrict__ Ahi, const __nv_bfloat16* __restrict__ Alo,
               const __nv_bfloat16* __restrict__ Bhi, const __nv_bfloat16* __restrict__ Blo,
               const float* __restrict__ bias, float* __restrict__ C,
               __nv_bfloat16* __restrict__ Chi, __nv_bfloat16* __restrict__ Clo,
               int N, int mode)
{
    extern __shared__ __nv_bfloat16 smb[];
    const uint32_t sb = smem_u32(smb);
    const int tid  = threadIdx.x;
    const int lane = tid & 31;
    const int wid  = tid >> 5;
    const int wm   = wid & 3;
    const int wn   = wid >> 2;
    const int m0   = blockIdx.y * 128;
    const int n0   = blockIdx.x * 128;

    // per-thread fixed load slot
    const int l_tile = tid >> 6;                  // 0..3 (64 thr per tile)
    const int l_idx  = 0;                         // placeholder
    (void)l_idx;

    auto load_stage = [&](uint32_t stoff, int k0) {
#pragma unroll
        for (int i = 0; i < 8; i++) {
            int c    = tid + i * 256;
            int tile = c >> 9;
            int idx  = c & 511;
            int row  = idx >> 2;
            int seg  = idx & 3;
            const __nv_bfloat16* src;
            if      (tile == 0) src = Ahi + (size_t)(m0 + row) * GK + k0 + seg * 8;
            else if (tile == 1) src = Alo + (size_t)(m0 + row) * GK + k0 + seg * 8;
            else if (tile == 2) src = Bhi + (size_t)(n0 + row) * GK + k0 + seg * 8;
            else                src = Blo + (size_t)(n0 + row) * GK + k0 + seg * 8;
            cp_async16(sb + stoff + (uint32_t)tile * GTILE_B + gsw(row, seg), src);
        }
        asm volatile("cp.async.commit_group;" ::: "memory");
    };

    float acc[2][8][4];
#pragma unroll
    for (int mt = 0; mt < 2; mt++)
#pragma unroll
        for (int nt = 0; nt < 8; nt++)
#pragma unroll
            for (int q = 0; q < 4; q++) acc[mt][nt][q] = 0.f;

    load_stage(0, 0);
    load_stage(GSTG_B, 32);

    const int lr = lane & 15;
    const int ls = lane >> 4;            // 0/1: second 8-K half

    auto step = [&](int c, uint32_t stoff) {
        asm volatile("cp.async.wait_group 1;" ::: "memory");
        __syncthreads();
        if (c + 2 < GNC) {
            uint32_t st2 = stoff + 2 * GSTG_B;
            if (st2 >= GSMEM) st2 -= GSMEM;
            load_stage(st2, (c + 2) * 32);
        } else {
            asm volatile("cp.async.commit_group;" ::: "memory");
        }
        const uint32_t so = sb + stoff;
#pragma unroll
        for (int ks = 0; ks < 2; ks++) {           // 16-K steps
            const int s = ks * 2 + ls;
            uint32_t ahi[2][4], alo[2][4];
#pragma unroll
            for (int mt = 0; mt < 2; mt++) {
                uint32_t ad = so + gsw(wm * 32 + mt * 16 + lr, s);
                ldmat_x4(ad, ahi[mt][0], ahi[mt][1], ahi[mt][2], ahi[mt][3]);
                ldmat_x4(ad + GTILE_B, alo[mt][0], alo[mt][1], alo[mt][2], alo[mt][3]);
            }
            uint32_t bhi[8][2], blo[8][2];
#pragma unroll
            for (int bt = 0; bt < 4; bt++) {
                uint32_t ad = so + 2 * GTILE_B + gsw(wn * 64 + bt * 16 + lr, s);
                uint32_t r0, r1, r2, r3;
                ldmat_x4(ad, r0, r1, r2, r3);
                bhi[bt * 2][0] = r0; bhi[bt * 2][1] = r2;
                bhi[bt * 2 + 1][0] = r1; bhi[bt * 2 + 1][1] = r3;
                ldmat_x4(ad + GTILE_B, r0, r1, r2, r3);
                blo[bt * 2][0] = r0; blo[bt * 2][1] = r2;
                blo[bt * 2 + 1][0] = r1; blo[bt * 2 + 1][1] = r3;
            }
#pragma unroll
            for (int mt = 0; mt < 2; mt++)
#pragma unroll
                for (int nt = 0; nt < 8; nt++) {
                    mma16816(acc[mt][nt], ahi[mt], bhi[nt]);
                    mma16816(acc[mt][nt], ahi[mt], blo[nt]);
                    mma16816(acc[mt][nt], alo[mt], bhi[nt]);
                }
        }
    };

    // GNC = 32 = 3*10 + 2; stage offsets literal per call
#pragma unroll 1
    for (int cb = 0; cb < 30; cb += 3) {
        step(cb,     0u);
        step(cb + 1, GSTG_B);
        step(cb + 2, 2u * GSTG_B);
    }
    step(30, 0u);
    step(31, GSTG_B);

    const int g = lane >> 2, t = lane & 3;
#pragma unroll
    for (int mt = 0; mt < 2; mt++) {
        const int r0 = m0 + wm * 32 + mt * 16 + g;
#pragma unroll
        for (int nt = 0; nt < 8; nt++) {
            const int col = n0 + wn * 64 + nt * 8 + 2 * t;
            float2 bv = *(const float2*)(bias + col);
            float v0 = acc[mt][nt][0] + bv.x, v1 = acc[mt][nt][1] + bv.y;
            float v2 = acc[mt][nt][2] + bv.x, v3 = acc[mt][nt][3] + bv.y;
            if (mode == 0) {
                *(float2*)(C + (size_t)r0 * N + col)       = make_float2(v0, v1);
                *(float2*)(C + (size_t)(r0 + 8) * N + col) = make_float2(v2, v3);
            } else {
                uint32_t h, l;
                split_pair(v0, v1, h, l);
                *(uint32_t*)(Chi + (size_t)r0 * N + col) = h;
                *(uint32_t*)(Clo + (size_t)r0 * N + col) = l;
                split_pair(v2, v3, h, l);
                *(uint32_t*)(Chi + (size_t)(r0 + 8) * N + col) = h;
                *(uint32_t*)(Clo + (size_t)(r0 + 8) * N + col) = l;
            }
        }
    }
}

// -------------------- tensor-core flash attention (2 CTAs/SM) --------------------
// grid (S/128, H, B); 256 thr = 8 warps x 16 q-rows; KV tiles of 64 rows.
// smem: Qhi,Qlo (16KB each) + 2 stages x {Khi,Klo,Vhi,Vlo} (8KB each) = 96KB.
// 128B rows, XOR-8 swizzle.
#define ATILE_A 8192u
#define ASTG_A  (4u * ATILE_A)           // 32768
#define AQSZ    16384u                   // one Q component
#define ASMEM_A (2u * AQSZ + 2u * ASTG_A) // 98304

#define SC_LOG2E 0.180336879f            // 0.125 * log2(e)
#define MASKED_U (-1442.69504f)          // -1000 * log2(e)

__device__ __forceinline__ uint32_t asw(int row, int seg) {
    return (uint32_t)(row * 128 + ((seg ^ (row & 7)) << 4));
}

__global__ void __launch_bounds__(256, 2)
attn_mma(const __nv_bfloat16* __restrict__ qh_g, const __nv_bfloat16* __restrict__ ql_g,
         const int* __restrict__ mask,
         __nv_bfloat16* __restrict__ chi, __nv_bfloat16* __restrict__ clo)
{
    extern __shared__ __nv_bfloat16 sma[];
    const uint32_t sb = smem_u32(sma);
    const int tid  = threadIdx.x;
    const int lane = tid & 31;
    const int w    = tid >> 5;
    const int q0   = blockIdx.x * 128;
    const int h    = blockIdx.y;
    const int b    = blockIdx.z;
    const size_t rowbase = (size_t)b * S_;

    const int lr = lane & 15;
    const int ls = lane >> 4;            // 16B seg selector

    // ---- Q loads (hi+lo): 2048 chunks, 8 per thread ----
#pragma unroll
    for (int i = 0; i < 8; i++) {
        int c = tid + i * 256;
        int comp = c >> 10, idx = c & 1023;
        int row = idx >> 3, seg = idx & 7;
        const __nv_bfloat16* src = (comp ? ql_g : qh_g) +
            (rowbase + q0 + row) * N1_ + h * DH_ + seg * 8;
        cp_async16(sb + comp * AQSZ + asw(row, seg), src);
    }
    asm volatile("cp.async.commit_group;" ::: "memory");

    auto load_kv = [&](int kt, int st) {
#pragma unroll
        for (int i = 0; i < 8; i++) {
            int c = tid + i * 256;
            int tile = c >> 9, idx = c & 511;
            int row = idx >> 3, seg = idx & 7;
            const __nv_bfloat16* base = (tile & 1) ? ql_g : qh_g;
            int coloff = (tile < 2) ? D_ : 2 * D_;
            const __nv_bfloat16* src = base +
                (rowbase + kt * 64 + row) * N1_ + coloff + h * DH_ + seg * 8;
            cp_async16(sb + 2 * AQSZ + (uint32_t)st * ASTG_A +
                       (uint32_t)tile * ATILE_A + asw(row, seg), src);
        }
        asm volatile("cp.async.commit_group;" ::: "memory");
    };

    load_kv(0, 0);
    asm volatile("cp.async.wait_group 0;" ::: "memory");
    __syncthreads();

    // ---- preload Q fragments (4 k-steps, hi+lo) ----
    uint32_t qfh[4][4], qfl[4][4];
#pragma unroll
    for (int ks = 0; ks < 4; ks++) {
        uint32_t ad = sb + asw(w * 16 + lr, ks * 2 + ls);
        ldmat_x4(ad, qfh[ks][0], qfh[ks][1], qfh[ks][2], qfh[ks][3]);
        ldmat_x4(ad + AQSZ, qfl[ks][0], qfl[ks][1], qfl[ks][2], qfl[ks][3]);
    }

    float o[8][4];
#pragma unroll
    for (int d = 0; d < 8; d++)
#pragma unroll
        for (int q = 0; q < 4; q++) o[d][q] = 0.f;
    float m0 = -1e30f, m1 = -1e30f, l0 = 0.f, l1 = 0.f;

    const int g  = lane >> 2;
    const int tq = lane & 3;
    const int r0g = q0 + w * 16 + g;
    const int lrow = ((lane >> 3) & 1) * 8 + (lane & 7);

    for (int kt = 0; kt < S_ / 64; kt++) {
        if (kt > 0) {
            asm volatile("cp.async.wait_group 0;" ::: "memory");
        }
        __syncthreads();
        if (kt + 1 < S_ / 64) load_kv(kt + 1, (kt + 1) & 1);

        const uint32_t kvb = sb + 2 * AQSZ + (uint32_t)(kt & 1) * ASTG_A;

        // ---- S = Q K^T ----
        float s[8][4];
#pragma unroll
        for (int nt = 0; nt < 8; nt++)
#pragma unroll
            for (int q = 0; q < 4; q++) s[nt][q] = 0.f;

#pragma unroll
        for (int idx = 0; idx < 16; idx++) {
            const int ks = idx >> 2, bt = idx & 3;
            uint32_t ad = kvb + asw(bt * 16 + lr, ks * 2 + ls);
            uint32_t h0, h1, h2, h3, e0, e1, e2, e3;
            ldmat_x4(ad, h0, h1, h2, h3);
            ldmat_x4(ad + ATILE_A, e0, e1, e2, e3);
            uint32_t bhE[2] = {h0, h2}, bhO[2] = {h1, h3};
            uint32_t blE[2] = {e0, e2}, blO[2] = {e1, e3};
            mma16816(s[2 * bt],     qfh[ks], bhE);
            mma16816(s[2 * bt],     qfh[ks], blE);
            mma16816(s[2 * bt],     qfl[ks], bhE);
            mma16816(s[2 * bt + 1], qfh[ks], bhO);
            mma16816(s[2 * bt + 1], qfh[ks], blO);
            mma16816(s[2 * bt + 1], qfl[ks], bhO);
        }

        // ---- scale + mask + online softmax (base-2) ----
        const int cb = kt * 64 + tq * 2;
        float mx0 = -1e30f, mx1 = -1e30f;
#pragma unroll
        for (int nt = 0; nt < 8; nt++) {
            int2 mv0 = __ldg((const int2*)(mask + (size_t)r0g * S_ + cb + nt * 8));
            int2 mv1 = __ldg((const int2*)(mask + (size_t)(r0g + 8) * S_ + cb + nt * 8));
            s[nt][0] = mv0.x ? s[nt][0] * SC_LOG2E : MASKED_U;
            s[nt][1] = mv0.y ? s[nt][1] * SC_LOG2E : MASKED_U;
            s[nt][2] = mv1.x ? s[nt][2] * SC_LOG2E : MASKED_U;
            s[nt][3] = mv1.y ? s[nt][3] * SC_LOG2E : MASKED_U;
            mx0 = fmaxf(mx0, fmaxf(s[nt][0], s[nt][1]));
            mx1 = fmaxf(mx1, fmaxf(s[nt][2], s[nt][3]));
        }
        mx0 = fmaxf(mx0, __shfl_xor_sync(0xffffffffu, mx0, 1));
        mx0 = fmaxf(mx0, __shfl_xor_sync(0xffffffffu, mx0, 2));
        mx1 = fmaxf(mx1, __shfl_xor_sync(0xffffffffu, mx1, 1));
        mx1 = fmaxf(mx1, __shfl_xor_sync(0xffffffffu, mx1, 2));
        const float mn0 = fmaxf(m0, mx0), mn1 = fmaxf(m1, mx1);
        const float c0 = ex2f(m0 - mn0), c1 = ex2f(m1 - mn1);
        m0 = mn0; m1 = mn1;
        float rs0 = 0.f, rs1 = 0.f;
#pragma unroll
        for (int nt = 0; nt < 8; nt++) {
            s[nt][0] = ex2f(s[nt][0] - mn0);
            s[nt][1] = ex2f(s[nt][1] - mn0);
            s[nt][2] = ex2f(s[nt][2] - mn1);
            s[nt][3] = ex2f(s[nt][3] - mn1);
            rs0 += s[nt][0] + s[nt][1];
            rs1 += s[nt][2] + s[nt][3];
        }
        l0 = l0 * c0 + rs0;
        l1 = l1 * c1 + rs1;
#pragma unroll
        for (int d = 0; d < 8; d++) {
            o[d][0] *= c0; o[d][1] *= c0; o[d][2] *= c1; o[d][3] *= c1;
        }

        // ---- O += P V ----
        const uint32_t vb = kvb + 2 * ATILE_A;
        uint32_t ph[4], pl[4];
#pragma unroll
        for (int idx = 0; idx < 16; idx++) {
            const int kk = idx >> 2, nb = idx & 3;
            if (nb == 0) {
                split_pair(s[2 * kk][0],     s[2 * kk][1],     ph[0], pl[0]);
                split_pair(s[2 * kk][2],     s[2 * kk][3],     ph[1], pl[1]);
                split_pair(s[2 * kk + 1][0], s[2 * kk + 1][1], ph[2], pl[2]);
                split_pair(s[2 * kk + 1][2], s[2 * kk + 1][3], ph[3], pl[3]);
            }
            uint32_t ad = vb + asw(kk * 16 + lrow, nb * 2 + ls);
            uint32_t v0, v1, v2, v3, u0, u1, u2, u3;
            ldmat_x4t(ad, v0, v1, v2, v3);
            ldmat_x4t(ad + ATILE_A, u0, u1, u2, u3);
            uint32_t bhE[2] = {v0, v1}, bhO[2] = {v2, v3};
            uint32_t blE[2] = {u0, u1}, blO[2] = {u2, u3};
            mma16816(o[2 * nb],     ph, bhE);
            mma16816(o[2 * nb],     ph, blE);
            mma16816(o[2 * nb],     pl, bhE);
            mma16816(o[2 * nb + 1], ph, bhO);
            mma16816(o[2 * nb + 1], ph, blO);
            mma16816(o[2 * nb + 1], pl, bhO);
        }
    }

    // ---- epilogue ----
    l0 += __shfl_xor_sync(0xffffffffu, l0, 1);
    l0 += __shfl_xor_sync(0xffffffffu, l0, 2);
    l1 += __shfl_xor_sync(0xffffffffu, l1, 1);
    l1 += __shfl_xor_sync(0xffffffffu, l1, 2);
    const float i0 = 1.f / l0, i1 = 1.f / l1;
    const size_t ra = (rowbase + q0 + w * 16 + g) * D_ + h * DH_;
    const size_t rb = ra + 8 * D_;
#pragma unroll
    for (int d = 0; d < 8; d++) {
        const int col = d * 8 + tq * 2;
        uint32_t hp, lp;
        split_pair(o[d][0] * i0, o[d][1] * i0, hp, lp);
        *(uint32_t*)(chi + ra + col) = hp;
        *(uint32_t*)(clo + ra + col) = lp;
        split_pair(o[d][2] * i1, o[d][3] * i1, hp, lp);
        *(uint32_t*)(chi + rb + col) = hp;
        *(uint32_t*)(clo + rb + col) = lp;
    }
}

// -------------------- launch --------------------
extern "C" void kernel_launch(void* const* d_in, const int* in_sizes, int n_in,
                              void* d_out, int out_size)
{
    const float* x    = nullptr;
    const float* Wqkv = nullptr;
    const float* bqkv = nullptr;
    const float* Wout = nullptr;
    const float* bout = nullptr;
    const int*   mask = nullptr;

    for (int i = 0; i < n_in; i++) {
        long n = in_sizes[i];
        if      (n == (long)M_ * D_)   x    = (const float*)d_in[i];
        else if (n == (long)D_ * N1_)  Wqkv = (const float*)d_in[i];
        else if (n == (long)N1_)       bqkv = (const float*)d_in[i];
        else if (n == (long)D_ * D_)   Wout = (const float*)d_in[i];
        else if (n == (long)D_)        bout = (const float*)d_in[i];
        else if (n == (long)S_ * S_)   mask = (const int*)d_in[i];
    }

    __nv_bfloat16 *xhi, *xlo, *qkvhi, *qkvlo, *chi, *clo, *w1hi, *w1lo, *w2hi, *w2lo;
    cudaGetSymbolAddress((void**)&xhi, g_xhi);
    cudaGetSymbolAddress((void**)&xlo, g_xlo);
    cudaGetSymbolAddress((void**)&qkvhi, g_qkvhi);
    cudaGetSymbolAddress((void**)&qkvlo, g_qkvlo);
    cudaGetSymbolAddress((void**)&chi, g_chi);
    cudaGetSymbolAddress((void**)&clo, g_clo);
    cudaGetSymbolAddress((void**)&w1hi, g_w1hi);
    cudaGetSymbolAddress((void**)&w1lo, g_w1lo);
    cudaGetSymbolAddress((void**)&w2hi, g_w2hi);
    cudaGetSymbolAddress((void**)&w2lo, g_w2lo);

    cudaFuncSetAttribute(gemm_mma_split,
                         cudaFuncAttributeMaxDynamicSharedMemorySize, GSMEM);
    cudaFuncSetAttribute(attn_mma,
                         cudaFuncAttributeMaxDynamicSharedMemorySize, ASMEM_A);

    split_kernel<<<(M_ * D_) / (256 * 4), 256>>>(x, xhi, xlo);
    transpose_split_kernel<<<dim3(N1_ / 32, D_ / 32), dim3(32, 8)>>>(Wqkv, w1hi, w1lo, D_, N1_);
    transpose_split_kernel<<<dim3(D_ / 32, D_ / 32), dim3(32, 8)>>>(Wout, w2hi, w2lo, D_, D_);

    gemm_mma_split<<<dim3(N1_ / 128, M_ / 128), 256, GSMEM>>>(
        xhi, xlo, w1hi, w1lo, bqkv, nullptr, qkvhi, qkvlo, N1_, 1);

    attn_mma<<<dim3(S_ / 128, H_, B_), 256, ASMEM_A>>>(qkvhi, qkvlo, mask, chi, clo);

    gemm_mma_split<<<dim3(D_ / 128, M_ / 128), 256, GSMEM>>>(
        chi, clo, w2hi, w2lo, bout, (float*)d_out, nullptr, nullptr, D_, 0);
}